// round 1
// baseline (speedup 1.0000x reference)
#include <cuda_runtime.h>
#include <cstdint>

// ---------------- problem constants ----------------
#define NB   16
#define NC   256
#define HW   1024
#define DIM  1024

// ---------------- scratch (device globals; no allocation) ----------------
__device__ float g_x[NB * NC * HW];            // cdc output, then LN'd in place
__device__ float g_vspa[NB * NC * HW];
__device__ float g_vfreq[NB * NC * HW];
__device__ float g_qk[NB * NC * 2 * HW];       // [b, c, 2048]: q | k
__device__ float g_qT[NB * HW * NC];           // [b, n, c]
__device__ float g_att[NB * HW * HW];          // [b, n, m]
__device__ float g_p[NB * HW * HW];            // att@W^T (+bias), softmaxed (reused spa/frq)
__device__ float g_wqkT[DIM * 2 * DIM];        // [1024, 2048]
__device__ float g_wspaT[DIM * DIM];
__device__ float g_wfrqT[DIM * DIM];

// ---------------- SGEMM: C[m,n] = alpha*sum_k A[m,k]B[k,n] + biasRow[m] + biasCol[n] + Add[m,n]
// Requires M%128==0, N%128==0, K%16==0. All pointers 16B aligned per-row.
#define BM 128
#define BN 128
#define BK 16
#define TM 8
#define TN 8

__global__ __launch_bounds__(256, 2)
void sgemm(const float* __restrict__ A, int lda, long long sA,
           const float* __restrict__ B, int ldb, long long sB,
           const float* __restrict__ Add, long long sAdd,
           const float* __restrict__ biasRow, const float* __restrict__ biasCol,
           float* __restrict__ C, int ldc, long long sC,
           int K, float alpha)
{
    __shared__ float As[BK][BM];
    __shared__ float Bs[BK][BN];

    const long long bz = blockIdx.z;
    A += bz * sA;
    B += bz * sB;
    C += bz * sC;
    if (Add) Add += bz * sAdd;

    const int bm = blockIdx.y * BM;
    const int bn = blockIdx.x * BN;
    const int tid = threadIdx.x;
    const int tx = tid & 15;
    const int ty = tid >> 4;

    float acc[TM][TN];
#pragma unroll
    for (int i = 0; i < TM; i++)
#pragma unroll
        for (int j = 0; j < TN; j++) acc[i][j] = 0.f;

    for (int k0 = 0; k0 < K; k0 += BK) {
        // A tile: 128 rows x 16 k -> store transposed As[k][m]
#pragma unroll
        for (int l = 0; l < 2; l++) {
            int idx = tid + l * 256;       // 0..511 float4 slots
            int r   = idx >> 2;            // row within tile
            int c4  = (idx & 3) * 4;       // k offset
            float4 v = *(const float4*)(A + (long long)(bm + r) * lda + k0 + c4);
            As[c4 + 0][r] = v.x;
            As[c4 + 1][r] = v.y;
            As[c4 + 2][r] = v.z;
            As[c4 + 3][r] = v.w;
        }
        // B tile: 16 k x 128 n
#pragma unroll
        for (int l = 0; l < 2; l++) {
            int idx = tid + l * 256;
            int r   = idx >> 5;            // k row
            int c4  = (idx & 31) * 4;      // n offset
            *(float4*)&Bs[r][c4] =
                *(const float4*)(B + (long long)(k0 + r) * ldb + bn + c4);
        }
        __syncthreads();

#pragma unroll
        for (int kk = 0; kk < BK; kk++) {
            float a[TM], bb[TN];
#pragma unroll
            for (int i = 0; i < TM; i++) a[i] = As[kk][ty * TM + i];
#pragma unroll
            for (int j = 0; j < TN; j++) bb[j] = Bs[kk][tx * TN + j];
#pragma unroll
            for (int i = 0; i < TM; i++)
#pragma unroll
                for (int j = 0; j < TN; j++)
                    acc[i][j] = fmaf(a[i], bb[j], acc[i][j]);
        }
        __syncthreads();
    }

#pragma unroll
    for (int i = 0; i < TM; i++) {
        const int m = bm + ty * TM + i;
        const float br = biasRow ? biasRow[m] : 0.f;
        const long long rowoff = (long long)m * ldc;
#pragma unroll
        for (int j = 0; j < TN; j += 4) {
            const int n = bn + tx * TN + j;
            float4 r;
            r.x = alpha * acc[i][j + 0] + br;
            r.y = alpha * acc[i][j + 1] + br;
            r.z = alpha * acc[i][j + 2] + br;
            r.w = alpha * acc[i][j + 3] + br;
            if (biasCol) {
                const float4 bc = *(const float4*)(biasCol + n);
                r.x += bc.x; r.y += bc.y; r.z += bc.z; r.w += bc.w;
            }
            if (Add) {
                const float4 a4 = *(const float4*)(Add + rowoff + n);
                r.x += a4.x; r.y += a4.y; r.z += a4.z; r.w += a4.w;
            }
            *(float4*)(C + rowoff + n) = r;
        }
    }
}

// ---------------- LayerNorm over rows of length 1024 (in place) ----------------
__global__ __launch_bounds__(256)
void layernorm_k(float* __restrict__ x, const float* __restrict__ g,
                 const float* __restrict__ bt)
{
    __shared__ float sh[8];
    __shared__ float stat[2];
    float* row = x + (long long)blockIdx.x * 1024;
    const int tid  = threadIdx.x;
    const int lane = tid & 31;
    const int wid  = tid >> 5;

    float4 v = ((const float4*)row)[tid];

    float s = v.x + v.y + v.z + v.w;
#pragma unroll
    for (int o = 16; o > 0; o >>= 1) s += __shfl_xor_sync(0xffffffffu, s, o);
    if (lane == 0) sh[wid] = s;
    __syncthreads();
    if (wid == 0) {
        float t = (lane < 8) ? sh[lane] : 0.f;
#pragma unroll
        for (int o = 4; o > 0; o >>= 1) t += __shfl_xor_sync(0xffffffffu, t, o);
        if (lane == 0) stat[0] = t;
    }
    __syncthreads();
    const float mean = stat[0] * (1.f / 1024.f);

    const float dx = v.x - mean, dy = v.y - mean, dz = v.z - mean, dw = v.w - mean;
    float ss = dx * dx + dy * dy + dz * dz + dw * dw;
#pragma unroll
    for (int o = 16; o > 0; o >>= 1) ss += __shfl_xor_sync(0xffffffffu, ss, o);
    __syncthreads();               // protect sh reuse
    if (lane == 0) sh[wid] = ss;
    __syncthreads();
    if (wid == 0) {
        float t = (lane < 8) ? sh[lane] : 0.f;
#pragma unroll
        for (int o = 4; o > 0; o >>= 1) t += __shfl_xor_sync(0xffffffffu, t, o);
        if (lane == 0) stat[1] = t;
    }
    __syncthreads();
    const float inv = rsqrtf(stat[1] * (1.f / 1024.f) + 1e-5f);

    const float4 gg = ((const float4*)g)[tid];
    const float4 bb = ((const float4*)bt)[tid];
    float4 o4;
    o4.x = dx * inv * gg.x + bb.x;
    o4.y = dy * inv * gg.y + bb.y;
    o4.z = dz * inv * gg.z + bb.z;
    o4.w = dw * inv * gg.w + bb.w;
    ((float4*)row)[tid] = o4;
}

// ---------------- row softmax over length-1024 rows (in place) ----------------
__global__ __launch_bounds__(256)
void softmax_k(float* __restrict__ p)
{
    __shared__ float sh[8];
    __shared__ float stat[2];
    float* row = p + (long long)blockIdx.x * 1024;
    const int tid  = threadIdx.x;
    const int lane = tid & 31;
    const int wid  = tid >> 5;

    float4 v = ((const float4*)row)[tid];
    float mx = fmaxf(fmaxf(v.x, v.y), fmaxf(v.z, v.w));
#pragma unroll
    for (int o = 16; o > 0; o >>= 1)
        mx = fmaxf(mx, __shfl_xor_sync(0xffffffffu, mx, o));
    if (lane == 0) sh[wid] = mx;
    __syncthreads();
    if (wid == 0) {
        float t = (lane < 8) ? sh[lane] : -3.4e38f;
#pragma unroll
        for (int o = 4; o > 0; o >>= 1)
            t = fmaxf(t, __shfl_xor_sync(0xffffffffu, t, o));
        if (lane == 0) stat[0] = t;
    }
    __syncthreads();
    const float m = stat[0];

    v.x = __expf(v.x - m);
    v.y = __expf(v.y - m);
    v.z = __expf(v.z - m);
    v.w = __expf(v.w - m);
    float s = v.x + v.y + v.z + v.w;
#pragma unroll
    for (int o = 16; o > 0; o >>= 1) s += __shfl_xor_sync(0xffffffffu, s, o);
    __syncthreads();
    if (lane == 0) sh[wid] = s;
    __syncthreads();
    if (wid == 0) {
        float t = (lane < 8) ? sh[lane] : 0.f;
#pragma unroll
        for (int o = 4; o > 0; o >>= 1) t += __shfl_xor_sync(0xffffffffu, t, o);
        if (lane == 0) stat[1] = t;
    }
    __syncthreads();
    const float inv = 1.f / stat[1];
    v.x *= inv; v.y *= inv; v.z *= inv; v.w *= inv;
    ((float4*)row)[tid] = v;
}

// ---------------- tiled transpose: out[c, r] = in[r, c] ----------------
__global__ __launch_bounds__(256)
void transpose_k(const float* __restrict__ in, int ldi, long long sIn,
                 float* __restrict__ out, int ldo, long long sOut)
{
    __shared__ float t[32][33];
    in  += (long long)blockIdx.z * sIn;
    out += (long long)blockIdx.z * sOut;
    const int r0 = blockIdx.y * 32;
    const int c0 = blockIdx.x * 32;
    const int x = threadIdx.x;   // 32
    const int y = threadIdx.y;   // 8
#pragma unroll
    for (int i = 0; i < 32; i += 8)
        t[y + i][x] = in[(long long)(r0 + y + i) * ldi + c0 + x];
    __syncthreads();
#pragma unroll
    for (int i = 0; i < 32; i += 8)
        out[(long long)(c0 + y + i) * ldo + r0 + x] = t[x][y + i];
}

// ---------------- launcher ----------------
extern "C" void kernel_launch(void* const* d_in, const int* in_sizes, int n_in,
                              void* d_out, int out_size)
{
    const float* x_spa  = (const float*)d_in[0];
    const float* x_freq = (const float*)d_in[1];
    const float* w_cdc  = (const float*)d_in[2];
    const float* b_cdc  = (const float*)d_in[3];
    const float* w_sv   = (const float*)d_in[4];
    const float* b_sv   = (const float*)d_in[5];
    const float* w_fv   = (const float*)d_in[6];
    const float* b_fv   = (const float*)d_in[7];
    const float* ln_w   = (const float*)d_in[8];
    const float* ln_b   = (const float*)d_in[9];
    const float* w_qk   = (const float*)d_in[10];
    const float* w_spa  = (const float*)d_in[11];
    const float* b_spa  = (const float*)d_in[12];
    const float* w_frq  = (const float*)d_in[13];
    const float* b_frq  = (const float*)d_in[14];

    float* out_spa  = (float*)d_out;
    float* out_freq = (float*)d_out + (long long)NB * NC * HW;

    float *p_x, *p_vspa, *p_vfreq, *p_qk, *p_qT, *p_att, *p_p;
    float *p_wqkT, *p_wspaT, *p_wfrqT;
    cudaGetSymbolAddress((void**)&p_x,     g_x);
    cudaGetSymbolAddress((void**)&p_vspa,  g_vspa);
    cudaGetSymbolAddress((void**)&p_vfreq, g_vfreq);
    cudaGetSymbolAddress((void**)&p_qk,    g_qk);
    cudaGetSymbolAddress((void**)&p_qT,    g_qT);
    cudaGetSymbolAddress((void**)&p_att,   g_att);
    cudaGetSymbolAddress((void**)&p_p,     g_p);
    cudaGetSymbolAddress((void**)&p_wqkT,  g_wqkT);
    cudaGetSymbolAddress((void**)&p_wspaT, g_wspaT);
    cudaGetSymbolAddress((void**)&p_wfrqT, g_wfrqT);

    const long long sX   = (long long)NC * HW;        // 262144
    const long long sQK  = (long long)NC * 2 * HW;    // 524288
    const long long sQT  = (long long)HW * NC;        // 262144
    const long long sAtt = (long long)HW * HW;        // 1048576
    const dim3 tb(32, 8);
    const float scale = 0.03125f;                     // hw^-0.5 = 1/32

    // weight transposes
    transpose_k<<<dim3(1024 / 32, 2048 / 32, 1), tb>>>(w_qk, 1024, 0, p_wqkT, 2048, 0);
    transpose_k<<<dim3(1024 / 32, 1024 / 32, 1), tb>>>(w_spa, 1024, 0, p_wspaT, 1024, 0);
    transpose_k<<<dim3(1024 / 32, 1024 / 32, 1), tb>>>(w_frq, 1024, 0, p_wfrqT, 1024, 0);

    // X = w_cdc[:, :256] @ x_spa + b_cdc ; X += w_cdc[:, 256:] @ x_freq
    sgemm<<<dim3(HW / BN, NC / BM, NB), 256>>>(
        w_cdc, 512, 0, x_spa, 1024, sX, nullptr, 0, b_cdc, nullptr,
        p_x, 1024, sX, 256, 1.f);
    sgemm<<<dim3(HW / BN, NC / BM, NB), 256>>>(
        w_cdc + 256, 512, 0, x_freq, 1024, sX, p_x, sX, nullptr, nullptr,
        p_x, 1024, sX, 256, 1.f);

    // v_spa / v_freq
    sgemm<<<dim3(HW / BN, NC / BM, NB), 256>>>(
        w_sv, 256, 0, x_spa, 1024, sX, nullptr, 0, b_sv, nullptr,
        p_vspa, 1024, sX, 256, 1.f);
    sgemm<<<dim3(HW / BN, NC / BM, NB), 256>>>(
        w_fv, 256, 0, x_freq, 1024, sX, nullptr, 0, b_fv, nullptr,
        p_vfreq, 1024, sX, 256, 1.f);

    // LayerNorm rows of X
    layernorm_k<<<NB * NC, 256>>>(p_x, ln_w, ln_b);

    // qk = X @ w_qk^T   [256, 2048]
    sgemm<<<dim3(2048 / BN, NC / BM, NB), 256>>>(
        p_x, 1024, sX, p_wqkT, 2048, 0, nullptr, 0, nullptr, nullptr,
        p_qk, 2048, sQK, 1024, 1.f);

    // qT[b][n][c] = q[b][c][n]
    transpose_k<<<dim3(HW / 32, NC / 32, NB), tb>>>(p_qk, 2048, sQK, p_qT, 256, sQT);

    // att = (qT @ k) * scale   [1024, 1024], K = 256
    sgemm<<<dim3(HW / BN, HW / BM, NB), 256>>>(
        p_qT, 256, sQT, p_qk + 1024, 2048, sQK, nullptr, 0, nullptr, nullptr,
        p_att, 1024, sAtt, 256, scale);

    // ---- spatial branch ----
    sgemm<<<dim3(HW / BN, HW / BM, NB), 256>>>(
        p_att, 1024, sAtt, p_wspaT, 1024, 0, nullptr, 0, nullptr, b_spa,
        p_p, 1024, sAtt, 1024, 1.f);
    softmax_k<<<NB * HW, 256>>>(p_p);
    sgemm<<<dim3(HW / BN, NC / BM, NB), 256>>>(
        p_vspa, 1024, sX, p_p, 1024, sAtt, x_spa, sX, nullptr, nullptr,
        out_spa, 1024, sX, 1024, 1.f);

    // ---- frequency branch (reuses g_p) ----
    sgemm<<<dim3(HW / BN, HW / BM, NB), 256>>>(
        p_att, 1024, sAtt, p_wfrqT, 1024, 0, nullptr, 0, nullptr, b_frq,
        p_p, 1024, sAtt, 1024, 1.f);
    softmax_k<<<NB * HW, 256>>>(p_p);
    sgemm<<<dim3(HW / BN, NC / BM, NB), 256>>>(
        p_vfreq, 1024, sX, p_p, 1024, sAtt, x_freq, sX, nullptr, nullptr,
        out_freq, 1024, sX, 1024, 1.f);

    (void)in_sizes; (void)n_in; (void)out_size;
}

// round 2
// speedup vs baseline: 2.9597x; 2.9597x over previous
#include <cuda_runtime.h>
#include <cstdint>

// ---------------- problem constants ----------------
#define NB   16
#define NC   256
#define HW   1024
#define DIM  1024

// ---------------- scratch (device globals; no allocation) ----------------
__device__ float g_x[NB * NC * HW];            // cdc output, then LN'd (tf32-rounded)
__device__ float g_vspa[NB * NC * HW];
__device__ float g_vfreq[NB * NC * HW];
__device__ float g_qk[NB * NC * 2 * HW];       // [b, c, 2048]: q | k
__device__ float g_qT[NB * HW * NC];           // [b, n, c]
__device__ float g_att[NB * HW * HW];          // [b, n, m]
__device__ float g_p[NB * HW * HW];            // logits -> softmax probs (reused)
__device__ float g_wqkT[DIM * 2 * DIM];
__device__ float g_wspaT[DIM * DIM];
__device__ float g_wfrqT[DIM * DIM];
__device__ float g_xspar[NB * NC * HW];        // tf32-rounded copies of inputs
__device__ float g_xfreqr[NB * NC * HW];
__device__ float g_wcdcr[NC * 2 * NC];
__device__ float g_wsvr[NC * NC];
__device__ float g_wfvr[NC * NC];

// ---------------- helpers ----------------
__device__ __forceinline__ float tf32r(float x) {
    asm("cvt.rna.tf32.f32 %0, %1;" : "=f"(x) : "f"(x));
    return x;
}
__device__ __forceinline__ void cpasync16(uint32_t dst, const void* src) {
    asm volatile("cp.async.cg.shared.global [%0], [%1], 16;\n" :: "r"(dst), "l"(src));
}
__device__ __forceinline__ void cpcommit() {
    asm volatile("cp.async.commit_group;\n");
}
__device__ __forceinline__ void cpwait1() {
    asm volatile("cp.async.wait_group 1;\n");
}
__device__ __forceinline__ void mma_tf32(float* d, const uint32_t* a, const uint32_t* b) {
    asm volatile(
        "mma.sync.aligned.m16n8k8.row.col.f32.tf32.tf32.f32 "
        "{%0,%1,%2,%3}, {%4,%5,%6,%7}, {%8,%9}, {%0,%1,%2,%3};\n"
        : "+f"(d[0]), "+f"(d[1]), "+f"(d[2]), "+f"(d[3])
        : "r"(a[0]), "r"(a[1]), "r"(a[2]), "r"(a[3]), "r"(b[0]), "r"(b[1]));
}

// ---------------- tf32 tensor-core GEMM ----------------
// C[m,n] = alpha*sum_k A[m,k]*B[k,n] + biasRow[m] + biasCol[n] + Add[m,n]
// Operands A,B MUST already be tf32-rounded fp32. M%128==0, N%128==0, K%32==0.
#define BM 128
#define BN 128
#define BKT 32
#define AS_LD 36            // floats per A row in smem (pad 4)
#define BS_LD 136           // floats per B row in smem (pad 8)
#define AS_FLOATS (BM * AS_LD)            // 4608
#define BS_FLOATS (BKT * BS_LD)           // 4352
#define STAGE_FLOATS (AS_FLOATS + BS_FLOATS)   // 8960
#define STAGE_BYTES (STAGE_FLOATS * 4)         // 35840
#define NSTAGES 3
#define SMEM_BYTES (STAGE_BYTES * NSTAGES)     // 107520

__global__ __launch_bounds__(256, 1)
void sgemm_tc(const float* __restrict__ A, int lda, long long sA,
              const float* __restrict__ B, int ldb, long long sB,
              const float* __restrict__ Add, long long sAdd,
              const float* __restrict__ biasRow, const float* __restrict__ biasCol,
              float* __restrict__ C, int ldc, long long sC,
              int K, float alpha, int roundC)
{
    extern __shared__ float smem[];
    const uint32_t smem_u32 = (uint32_t)__cvta_generic_to_shared(smem);

    const long long bz = blockIdx.z;
    A += bz * sA;
    B += bz * sB;
    C += bz * sC;
    if (Add) Add += bz * sAdd;

    const int bm = blockIdx.y * BM;
    const int bn = blockIdx.x * BN;
    const int tid  = threadIdx.x;
    const int lane = tid & 31;
    const int wid  = tid >> 5;
    const int wm = wid >> 2;     // 0..1
    const int wn = wid & 3;      // 0..3
    const int rb = wm * 64;
    const int cb = wn * 32;
    const int lr = lane >> 2;    // 0..7
    const int lc = lane & 3;     // 0..3

    float acc[4][4][4];
#pragma unroll
    for (int i = 0; i < 4; i++)
#pragma unroll
        for (int j = 0; j < 4; j++)
#pragma unroll
            for (int v = 0; v < 4; v++) acc[i][j][v] = 0.f;

    // per-thread load slots
    const int a_row = tid >> 3;           // 0..31 (plus +32*i)
    const int a_k4  = (tid & 7) * 4;
    const int b_row = tid >> 5;           // 0..7 (plus +8*i)
    const int b_n4  = (tid & 31) * 4;

    const int T = K / BKT;

    // stage load: A tile 128x32, B tile 32x128 (16B cp.async each)
    auto load_stage = [&](int t, int s) {
        const int k0 = t * BKT;
        const uint32_t sa = smem_u32 + s * STAGE_BYTES;
        const uint32_t sb = sa + AS_FLOATS * 4;
#pragma unroll
        for (int i = 0; i < 4; i++) {
            const int r = a_row + i * 32;
            cpasync16(sa + (r * AS_LD + a_k4) * 4,
                      A + (long long)(bm + r) * lda + k0 + a_k4);
        }
#pragma unroll
        for (int i = 0; i < 4; i++) {
            const int r = b_row + i * 8;
            cpasync16(sb + (r * BS_LD + b_n4) * 4,
                      B + (long long)(k0 + r) * ldb + bn + b_n4);
        }
    };

    load_stage(0, 0); cpcommit();
    load_stage(1, 1); cpcommit();

    for (int t = 0; t < T; t++) {
        cpwait1();
        __syncthreads();
        if (t + 2 < T) load_stage(t + 2, (t + 2) % NSTAGES);
        cpcommit();

        const float* sA_ = smem + (t % NSTAGES) * STAGE_FLOATS;
        const float* sB_ = sA_ + AS_FLOATS;

#pragma unroll
        for (int kk = 0; kk < 4; kk++) {
            const int kb = kk * 8 + lc;
            uint32_t a[4][4];
#pragma unroll
            for (int mi = 0; mi < 4; mi++) {
                const int m0 = rb + mi * 16 + lr;
                a[mi][0] = __float_as_uint(sA_[m0 * AS_LD + kb]);
                a[mi][1] = __float_as_uint(sA_[(m0 + 8) * AS_LD + kb]);
                a[mi][2] = __float_as_uint(sA_[m0 * AS_LD + kb + 4]);
                a[mi][3] = __float_as_uint(sA_[(m0 + 8) * AS_LD + kb + 4]);
            }
#pragma unroll
            for (int ni = 0; ni < 4; ni++) {
                const int n0 = cb + ni * 8 + lr;
                uint32_t b[2];
                b[0] = __float_as_uint(sB_[kb * BS_LD + n0]);
                b[1] = __float_as_uint(sB_[(kb + 4) * BS_LD + n0]);
#pragma unroll
                for (int mi = 0; mi < 4; mi++)
                    mma_tf32(acc[mi][ni], a[mi], b);
            }
        }
    }

    // epilogue
#pragma unroll
    for (int mi = 0; mi < 4; mi++) {
#pragma unroll
        for (int half = 0; half < 2; half++) {
            const int r = bm + rb + mi * 16 + lr + half * 8;
            const float br = biasRow ? biasRow[r] : 0.f;
            const long long rowoff = (long long)r * ldc;
#pragma unroll
            for (int ni = 0; ni < 4; ni++) {
                const int c = bn + cb + ni * 8 + lc * 2;
                float f0 = alpha * acc[mi][ni][half * 2 + 0] + br;
                float f1 = alpha * acc[mi][ni][half * 2 + 1] + br;
                if (biasCol) {
                    const float2 bc = *(const float2*)(biasCol + c);
                    f0 += bc.x; f1 += bc.y;
                }
                if (Add) {
                    const float2 ad = *(const float2*)(Add + rowoff + c);
                    f0 += ad.x; f1 += ad.y;
                }
                if (roundC) { f0 = tf32r(f0); f1 = tf32r(f1); }
                float2 o; o.x = f0; o.y = f1;
                *(float2*)(C + rowoff + c) = o;
            }
        }
    }
}

// ---------------- tf32 rounding pass ----------------
__global__ __launch_bounds__(256)
void round_k(const float4* __restrict__ in, float4* __restrict__ out, int n4)
{
    int i = blockIdx.x * 256 + threadIdx.x;
    if (i < n4) {
        float4 v = in[i];
        v.x = tf32r(v.x); v.y = tf32r(v.y); v.z = tf32r(v.z); v.w = tf32r(v.w);
        out[i] = v;
    }
}

// ---------------- LayerNorm over rows of length 1024 (in place, tf32-rounded out) ----------------
__global__ __launch_bounds__(256)
void layernorm_k(float* __restrict__ x, const float* __restrict__ g,
                 const float* __restrict__ bt)
{
    __shared__ float sh[8];
    __shared__ float stat[2];
    float* row = x + (long long)blockIdx.x * 1024;
    const int tid  = threadIdx.x;
    const int lane = tid & 31;
    const int wid  = tid >> 5;

    float4 v = ((const float4*)row)[tid];

    float s = v.x + v.y + v.z + v.w;
#pragma unroll
    for (int o = 16; o > 0; o >>= 1) s += __shfl_xor_sync(0xffffffffu, s, o);
    if (lane == 0) sh[wid] = s;
    __syncthreads();
    if (wid == 0) {
        float t = (lane < 8) ? sh[lane] : 0.f;
#pragma unroll
        for (int o = 4; o > 0; o >>= 1) t += __shfl_xor_sync(0xffffffffu, t, o);
        if (lane == 0) stat[0] = t;
    }
    __syncthreads();
    const float mean = stat[0] * (1.f / 1024.f);

    const float dx = v.x - mean, dy = v.y - mean, dz = v.z - mean, dw = v.w - mean;
    float ss = dx * dx + dy * dy + dz * dz + dw * dw;
#pragma unroll
    for (int o = 16; o > 0; o >>= 1) ss += __shfl_xor_sync(0xffffffffu, ss, o);
    __syncthreads();
    if (lane == 0) sh[wid] = ss;
    __syncthreads();
    if (wid == 0) {
        float t = (lane < 8) ? sh[lane] : 0.f;
#pragma unroll
        for (int o = 4; o > 0; o >>= 1) t += __shfl_xor_sync(0xffffffffu, t, o);
        if (lane == 0) stat[1] = t;
    }
    __syncthreads();
    const float inv = rsqrtf(stat[1] * (1.f / 1024.f) + 1e-5f);

    const float4 gg = ((const float4*)g)[tid];
    const float4 bb = ((const float4*)bt)[tid];
    float4 o4;
    o4.x = tf32r(dx * inv * gg.x + bb.x);
    o4.y = tf32r(dy * inv * gg.y + bb.y);
    o4.z = tf32r(dz * inv * gg.z + bb.z);
    o4.w = tf32r(dw * inv * gg.w + bb.w);
    ((float4*)row)[tid] = o4;
}

// ---------------- row softmax over length-1024 rows (in place, tf32-rounded out) ----------------
__global__ __launch_bounds__(256)
void softmax_k(float* __restrict__ p)
{
    __shared__ float sh[8];
    __shared__ float stat[2];
    float* row = p + (long long)blockIdx.x * 1024;
    const int tid  = threadIdx.x;
    const int lane = tid & 31;
    const int wid  = tid >> 5;

    float4 v = ((const float4*)row)[tid];
    float mx = fmaxf(fmaxf(v.x, v.y), fmaxf(v.z, v.w));
#pragma unroll
    for (int o = 16; o > 0; o >>= 1)
        mx = fmaxf(mx, __shfl_xor_sync(0xffffffffu, mx, o));
    if (lane == 0) sh[wid] = mx;
    __syncthreads();
    if (wid == 0) {
        float t = (lane < 8) ? sh[lane] : -3.4e38f;
#pragma unroll
        for (int o = 4; o > 0; o >>= 1)
            t = fmaxf(t, __shfl_xor_sync(0xffffffffu, t, o));
        if (lane == 0) stat[0] = t;
    }
    __syncthreads();
    const float m = stat[0];

    v.x = __expf(v.x - m);
    v.y = __expf(v.y - m);
    v.z = __expf(v.z - m);
    v.w = __expf(v.w - m);
    float s = v.x + v.y + v.z + v.w;
#pragma unroll
    for (int o = 16; o > 0; o >>= 1) s += __shfl_xor_sync(0xffffffffu, s, o);
    __syncthreads();
    if (lane == 0) sh[wid] = s;
    __syncthreads();
    if (wid == 0) {
        float t = (lane < 8) ? sh[lane] : 0.f;
#pragma unroll
        for (int o = 4; o > 0; o >>= 1) t += __shfl_xor_sync(0xffffffffu, t, o);
        if (lane == 0) stat[1] = t;
    }
    __syncthreads();
    const float inv = 1.f / stat[1];
    float4 o4;
    o4.x = tf32r(v.x * inv);
    o4.y = tf32r(v.y * inv);
    o4.z = tf32r(v.z * inv);
    o4.w = tf32r(v.w * inv);
    ((float4*)row)[tid] = o4;
}

// ---------------- tiled transpose: out[c, r] = in[r, c] (optional tf32 round) ----------------
__global__ __launch_bounds__(256)
void transpose_k(const float* __restrict__ in, int ldi, long long sIn,
                 float* __restrict__ out, int ldo, long long sOut, int rnd)
{
    __shared__ float t[32][33];
    in  += (long long)blockIdx.z * sIn;
    out += (long long)blockIdx.z * sOut;
    const int r0 = blockIdx.y * 32;
    const int c0 = blockIdx.x * 32;
    const int x = threadIdx.x;   // 32
    const int y = threadIdx.y;   // 8
#pragma unroll
    for (int i = 0; i < 32; i += 8)
        t[y + i][x] = in[(long long)(r0 + y + i) * ldi + c0 + x];
    __syncthreads();
    if (rnd) {
#pragma unroll
        for (int i = 0; i < 32; i += 8)
            out[(long long)(c0 + y + i) * ldo + r0 + x] = tf32r(t[x][y + i]);
    } else {
#pragma unroll
        for (int i = 0; i < 32; i += 8)
            out[(long long)(c0 + y + i) * ldo + r0 + x] = t[x][y + i];
    }
}

// ---------------- launcher ----------------
extern "C" void kernel_launch(void* const* d_in, const int* in_sizes, int n_in,
                              void* d_out, int out_size)
{
    const float* x_spa  = (const float*)d_in[0];
    const float* x_freq = (const float*)d_in[1];
    const float* w_cdc  = (const float*)d_in[2];
    const float* b_cdc  = (const float*)d_in[3];
    const float* w_sv   = (const float*)d_in[4];
    const float* b_sv   = (const float*)d_in[5];
    const float* w_fv   = (const float*)d_in[6];
    const float* b_fv   = (const float*)d_in[7];
    const float* ln_w   = (const float*)d_in[8];
    const float* ln_b   = (const float*)d_in[9];
    const float* w_qk   = (const float*)d_in[10];
    const float* w_spa  = (const float*)d_in[11];
    const float* b_spa  = (const float*)d_in[12];
    const float* w_frq  = (const float*)d_in[13];
    const float* b_frq  = (const float*)d_in[14];

    float* out_spa  = (float*)d_out;
    float* out_freq = (float*)d_out + (long long)NB * NC * HW;

    float *p_x, *p_vspa, *p_vfreq, *p_qk, *p_qT, *p_att, *p_p;
    float *p_wqkT, *p_wspaT, *p_wfrqT;
    float *p_xspar, *p_xfreqr, *p_wcdcr, *p_wsvr, *p_wfvr;
    cudaGetSymbolAddress((void**)&p_x,      g_x);
    cudaGetSymbolAddress((void**)&p_vspa,   g_vspa);
    cudaGetSymbolAddress((void**)&p_vfreq,  g_vfreq);
    cudaGetSymbolAddress((void**)&p_qk,     g_qk);
    cudaGetSymbolAddress((void**)&p_qT,     g_qT);
    cudaGetSymbolAddress((void**)&p_att,    g_att);
    cudaGetSymbolAddress((void**)&p_p,      g_p);
    cudaGetSymbolAddress((void**)&p_wqkT,   g_wqkT);
    cudaGetSymbolAddress((void**)&p_wspaT,  g_wspaT);
    cudaGetSymbolAddress((void**)&p_wfrqT,  g_wfrqT);
    cudaGetSymbolAddress((void**)&p_xspar,  g_xspar);
    cudaGetSymbolAddress((void**)&p_xfreqr, g_xfreqr);
    cudaGetSymbolAddress((void**)&p_wcdcr,  g_wcdcr);
    cudaGetSymbolAddress((void**)&p_wsvr,   g_wsvr);
    cudaGetSymbolAddress((void**)&p_wfvr,   g_wfvr);

    static int smem_set = 0;
    if (!smem_set) {
        cudaFuncSetAttribute(sgemm_tc, cudaFuncAttributeMaxDynamicSharedMemorySize, SMEM_BYTES);
        smem_set = 1;
    }

    const long long sX   = (long long)NC * HW;        // 262144
    const long long sQK  = (long long)NC * 2 * HW;    // 524288
    const long long sQT  = (long long)HW * NC;        // 262144
    const long long sAtt = (long long)HW * HW;        // 1048576
    const dim3 tb(32, 8);
    const float scale = 0.03125f;                     // hw^-0.5 = 1/32

    // tf32-round raw inputs & conv weights into scratch copies
    round_k<<<(NB * NC * HW / 4 + 255) / 256, 256>>>((const float4*)x_spa,  (float4*)p_xspar,  NB * NC * HW / 4);
    round_k<<<(NB * NC * HW / 4 + 255) / 256, 256>>>((const float4*)x_freq, (float4*)p_xfreqr, NB * NC * HW / 4);
    round_k<<<(NC * 2 * NC / 4 + 255) / 256, 256>>>((const float4*)w_cdc, (float4*)p_wcdcr, NC * 2 * NC / 4);
    round_k<<<(NC * NC / 4 + 255) / 256, 256>>>((const float4*)w_sv, (float4*)p_wsvr, NC * NC / 4);
    round_k<<<(NC * NC / 4 + 255) / 256, 256>>>((const float4*)w_fv, (float4*)p_wfvr, NC * NC / 4);

    // weight transposes (rounded)
    transpose_k<<<dim3(1024 / 32, 2048 / 32, 1), tb>>>(w_qk, 1024, 0, p_wqkT, 2048, 0, 1);
    transpose_k<<<dim3(1024 / 32, 1024 / 32, 1), tb>>>(w_spa, 1024, 0, p_wspaT, 1024, 0, 1);
    transpose_k<<<dim3(1024 / 32, 1024 / 32, 1), tb>>>(w_frq, 1024, 0, p_wfrqT, 1024, 0, 1);

    // X = w_cdc[:, :256] @ x_spa + b_cdc ; X += w_cdc[:, 256:] @ x_freq
    sgemm_tc<<<dim3(HW / BN, NC / BM, NB), 256, SMEM_BYTES>>>(
        p_wcdcr, 512, 0, p_xspar, 1024, sX, nullptr, 0, b_cdc, nullptr,
        p_x, 1024, sX, 256, 1.f, 0);
    sgemm_tc<<<dim3(HW / BN, NC / BM, NB), 256, SMEM_BYTES>>>(
        p_wcdcr + 256, 512, 0, p_xfreqr, 1024, sX, p_x, sX, nullptr, nullptr,
        p_x, 1024, sX, 256, 1.f, 0);

    // v_spa / v_freq (rounded for final GEMM)
    sgemm_tc<<<dim3(HW / BN, NC / BM, NB), 256, SMEM_BYTES>>>(
        p_wsvr, 256, 0, p_xspar, 1024, sX, nullptr, 0, b_sv, nullptr,
        p_vspa, 1024, sX, 256, 1.f, 1);
    sgemm_tc<<<dim3(HW / BN, NC / BM, NB), 256, SMEM_BYTES>>>(
        p_wfvr, 256, 0, p_xfreqr, 1024, sX, nullptr, 0, b_fv, nullptr,
        p_vfreq, 1024, sX, 256, 1.f, 1);

    // LayerNorm rows of X (writes tf32-rounded)
    layernorm_k<<<NB * NC, 256>>>(p_x, ln_w, ln_b);

    // qk = X @ w_qk^T   [256, 2048] (rounded)
    sgemm_tc<<<dim3(2048 / BN, NC / BM, NB), 256, SMEM_BYTES>>>(
        p_x, 1024, sX, p_wqkT, 2048, 0, nullptr, 0, nullptr, nullptr,
        p_qk, 2048, sQK, 1024, 1.f, 1);

    // qT[b][n][c] = q[b][c][n] (already rounded, no re-round)
    transpose_k<<<dim3(HW / 32, NC / 32, NB), tb>>>(p_qk, 2048, sQK, p_qT, 256, sQT, 0);

    // att = (qT @ k) * scale   [1024, 1024], K = 256 (rounded)
    sgemm_tc<<<dim3(HW / BN, HW / BM, NB), 256, SMEM_BYTES>>>(
        p_qT, 256, sQT, p_qk + 1024, 2048, sQK, nullptr, 0, nullptr, nullptr,
        p_att, 1024, sAtt, 256, scale, 1);

    // ---- spatial branch ----
    sgemm_tc<<<dim3(HW / BN, HW / BM, NB), 256, SMEM_BYTES>>>(
        p_att, 1024, sAtt, p_wspaT, 1024, 0, nullptr, 0, nullptr, b_spa,
        p_p, 1024, sAtt, 1024, 1.f, 0);
    softmax_k<<<NB * HW, 256>>>(p_p);
    sgemm_tc<<<dim3(HW / BN, NC / BM, NB), 256, SMEM_BYTES>>>(
        p_vspa, 1024, sX, p_p, 1024, sAtt, x_spa, sX, nullptr, nullptr,
        out_spa, 1024, sX, 1024, 1.f, 0);

    // ---- frequency branch (reuses g_p) ----
    sgemm_tc<<<dim3(HW / BN, HW / BM, NB), 256, SMEM_BYTES>>>(
        p_att, 1024, sAtt, p_wfrqT, 1024, 0, nullptr, 0, nullptr, b_frq,
        p_p, 1024, sAtt, 1024, 1.f, 0);
    softmax_k<<<NB * HW, 256>>>(p_p);
    sgemm_tc<<<dim3(HW / BN, NC / BM, NB), 256, SMEM_BYTES>>>(
        p_vfreq, 1024, sX, p_p, 1024, sAtt, x_freq, sX, nullptr, nullptr,
        out_freq, 1024, sX, 1024, 1.f, 0);

    (void)in_sizes; (void)n_in; (void)out_size;
}

// round 4
// speedup vs baseline: 3.4174x; 1.1547x over previous
#include <cuda_runtime.h>
#include <cstdint>

// ---------------- problem constants ----------------
#define NB   16
#define NC   256
#define HW   1024
#define DIM  1024

// ---------------- scratch (device globals; no allocation) ----------------
__device__ float g_x[NB * NC * HW];            // cdc output, then LN'd (tf32-rounded)
__device__ float g_vspa[NB * NC * HW];
__device__ float g_vfreq[NB * NC * HW];
__device__ float g_qk[NB * NC * 2 * HW];       // [b, c, 2048]: q | k
__device__ float g_qT[NB * HW * NC];           // [b, n, c]
__device__ float g_att[NB * HW * HW];          // [b, n, m]
__device__ float g_p[NB * HW * HW];            // logits -> softmax probs (reused)
__device__ float g_wqkT[DIM * 2 * DIM];
__device__ float g_wspaT[DIM * DIM];
__device__ float g_wfrqT[DIM * DIM];
__device__ float g_xspar[NB * NC * HW];        // tf32-rounded copies of inputs
__device__ float g_xfreqr[NB * NC * HW];
__device__ float g_wcdcr[NC * 2 * NC];
__device__ float g_wsvr[NC * NC];
__device__ float g_wfvr[NC * NC];

// ---------------- helpers ----------------
__device__ __forceinline__ float tf32r(float x) {
    asm("cvt.rna.tf32.f32 %0, %1;" : "=f"(x) : "f"(x));
    return x;
}
__device__ __forceinline__ void cpasync16(uint32_t dst, const void* src) {
    asm volatile("cp.async.cg.shared.global [%0], [%1], 16;\n" :: "r"(dst), "l"(src));
}
__device__ __forceinline__ void cpcommit() {
    asm volatile("cp.async.commit_group;\n");
}
__device__ __forceinline__ void cpwait1() {
    asm volatile("cp.async.wait_group 1;\n");
}
__device__ __forceinline__ void cpwait0() {
    asm volatile("cp.async.wait_group 0;\n");
}
__device__ __forceinline__ void mma_tf32(float* d, const uint32_t* a, const uint32_t* b) {
    asm volatile(
        "mma.sync.aligned.m16n8k8.row.col.f32.tf32.tf32.f32 "
        "{%0,%1,%2,%3}, {%4,%5,%6,%7}, {%8,%9}, {%0,%1,%2,%3};\n"
        : "+f"(d[0]), "+f"(d[1]), "+f"(d[2]), "+f"(d[3])
        : "r"(a[0]), "r"(a[1]), "r"(a[2]), "r"(a[3]), "r"(b[0]), "r"(b[1]));
}

// ---------------- tf32 tensor-core GEMM ----------------
// C[m,n] = alpha*sum_k A[m,k]*B[k,n] + biasRow[m] + biasCol[n] + Add[m,n]
// Operands A,B MUST already be tf32-rounded fp32. M%128==0, N%128==0, K%32==0.
// 128 threads (4 warps, 2x2), warp tile 64x64, CTA tile 128x128x32, 3-stage cp.async.
#define BM 128
#define BN 128
#define BKT 32
#define AS_LD 36            // floats per A row in smem (pad 4): bank = 4m+k, conflict-free
#define BS_LD 136           // floats per B row in smem (pad 8): bank = 8k+n, conflict-free
#define AS_FLOATS (BM * AS_LD)            // 4608
#define BS_FLOATS (BKT * BS_LD)           // 4352
#define STAGE_FLOATS (AS_FLOATS + BS_FLOATS)   // 8960
#define STAGE_BYTES (STAGE_FLOATS * 4)         // 35840
#define NSTAGES 3
#define SMEM_BYTES (STAGE_BYTES * NSTAGES)     // 107520 -> 2 CTAs/SM (215KB of 228KB)

__global__ __launch_bounds__(128, 2)
void sgemm_tc(const float* __restrict__ A, int lda, long long sA,
              const float* __restrict__ B, int ldb, long long sB,
              const float* __restrict__ Add, long long sAdd,
              const float* __restrict__ biasRow, const float* __restrict__ biasCol,
              float* __restrict__ C, int ldc, long long sC,
              int K, float alpha, int roundC)
{
    extern __shared__ float smem[];
    const uint32_t smem_u32 = (uint32_t)__cvta_generic_to_shared(smem);

    const long long bz = blockIdx.z;
    A += bz * sA;
    B += bz * sB;
    C += bz * sC;
    if (Add) Add += bz * sAdd;

    const int bm = blockIdx.y * BM;
    const int bn = blockIdx.x * BN;
    const int tid  = threadIdx.x;
    const int lane = tid & 31;
    const int wid  = tid >> 5;
    const int wm = wid >> 1;     // 0..1
    const int wn = wid & 1;      // 0..1
    const int rb = wm * 64;
    const int cb = wn * 64;
    const int lr = lane >> 2;    // 0..7
    const int lc = lane & 3;     // 0..3

    float acc[4][8][4];
#pragma unroll
    for (int i = 0; i < 4; i++)
#pragma unroll
        for (int j = 0; j < 8; j++)
#pragma unroll
            for (int v = 0; v < 4; v++) acc[i][j][v] = 0.f;

    // per-thread cp.async slots (128 threads)
    const int a_row = tid >> 3;           // 0..15 (plus +16*u)
    const int a_k4  = (tid & 7) * 4;
    const int b_row = tid >> 5;           // 0..3 (plus +4*u)
    const int b_n4  = (tid & 31) * 4;

    const int T = K / BKT;

    // stage load: A tile 128x32 (16B chunks), B tile 32x128
    auto load_stage = [&](int t, int s) {
        const int k0 = t * BKT;
        const uint32_t sa = smem_u32 + s * STAGE_BYTES;
        const uint32_t sb = sa + AS_FLOATS * 4;
#pragma unroll
        for (int u = 0; u < 8; u++) {
            const int r = a_row + u * 16;
            cpasync16(sa + (r * AS_LD + a_k4) * 4,
                      A + (long long)(bm + r) * lda + k0 + a_k4);
        }
#pragma unroll
        for (int u = 0; u < 8; u++) {
            const int r = b_row + u * 4;
            cpasync16(sb + (r * BS_LD + b_n4) * 4,
                      B + (long long)(k0 + r) * ldb + bn + b_n4);
        }
    };

    load_stage(0, 0); cpcommit();
    if (T > 1) { load_stage(1, 1); cpcommit(); }

    for (int t = 0; t < T; t++) {
        if (t < T - 1) cpwait1(); else cpwait0();
        __syncthreads();
        if (t + 2 < T) { load_stage(t + 2, (t + 2) % NSTAGES); }
        cpcommit();

        const float* sA_ = smem + (t % NSTAGES) * STAGE_FLOATS;
        const float* sB_ = sA_ + AS_FLOATS;

#pragma unroll
        for (int kk = 0; kk < 4; kk++) {
            const int kb = kk * 8 + lc;
            uint32_t a[4][4];
#pragma unroll
            for (int mi = 0; mi < 4; mi++) {
                const int m0 = rb + mi * 16 + lr;
                a[mi][0] = __float_as_uint(sA_[m0 * AS_LD + kb]);
                a[mi][1] = __float_as_uint(sA_[(m0 + 8) * AS_LD + kb]);
                a[mi][2] = __float_as_uint(sA_[m0 * AS_LD + kb + 4]);
                a[mi][3] = __float_as_uint(sA_[(m0 + 8) * AS_LD + kb + 4]);
            }
            uint32_t b[8][2];
#pragma unroll
            for (int ni = 0; ni < 8; ni++) {
                const int n0 = cb + ni * 8 + lr;
                b[ni][0] = __float_as_uint(sB_[kb * BS_LD + n0]);
                b[ni][1] = __float_as_uint(sB_[(kb + 4) * BS_LD + n0]);
            }
#pragma unroll
            for (int mi = 0; mi < 4; mi++)
#pragma unroll
                for (int ni = 0; ni < 8; ni++)
                    mma_tf32(acc[mi][ni], a[mi], b[ni]);
        }
        __syncthreads();
    }

    // epilogue
#pragma unroll
    for (int mi = 0; mi < 4; mi++) {
#pragma unroll
        for (int half = 0; half < 2; half++) {
            const int r = bm + rb + mi * 16 + lr + half * 8;
            const float br = biasRow ? biasRow[r] : 0.f;
            const long long rowoff = (long long)r * ldc;
#pragma unroll
            for (int ni = 0; ni < 8; ni++) {
                const int c = bn + cb + ni * 8 + lc * 2;
                float f0 = alpha * acc[mi][ni][half * 2 + 0] + br;
                float f1 = alpha * acc[mi][ni][half * 2 + 1] + br;
                if (biasCol) {
                    const float2 bc = *(const float2*)(biasCol + c);
                    f0 += bc.x; f1 += bc.y;
                }
                if (Add) {
                    const float2 ad = *(const float2*)(Add + rowoff + c);
                    f0 += ad.x; f1 += ad.y;
                }
                if (roundC) { f0 = tf32r(f0); f1 = tf32r(f1); }
                float2 o; o.x = f0; o.y = f1;
                *(float2*)(C + rowoff + c) = o;
            }
        }
    }
}

// ---------------- tf32 rounding pass ----------------
__global__ __launch_bounds__(256)
void round_k(const float4* __restrict__ in, float4* __restrict__ out, int n4)
{
    int i = blockIdx.x * 256 + threadIdx.x;
    if (i < n4) {
        float4 v = in[i];
        v.x = tf32r(v.x); v.y = tf32r(v.y); v.z = tf32r(v.z); v.w = tf32r(v.w);
        out[i] = v;
    }
}

// ---------------- LayerNorm over rows of length 1024 (in place, tf32-rounded out) ----------------
__global__ __launch_bounds__(256)
void layernorm_k(float* __restrict__ x, const float* __restrict__ g,
                 const float* __restrict__ bt)
{
    __shared__ float sh[8];
    __shared__ float stat[2];
    float* row = x + (long long)blockIdx.x * 1024;
    const int tid  = threadIdx.x;
    const int lane = tid & 31;
    const int wid  = tid >> 5;

    float4 v = ((const float4*)row)[tid];

    float s = v.x + v.y + v.z + v.w;
#pragma unroll
    for (int o = 16; o > 0; o >>= 1) s += __shfl_xor_sync(0xffffffffu, s, o);
    if (lane == 0) sh[wid] = s;
    __syncthreads();
    if (wid == 0) {
        float t = (lane < 8) ? sh[lane] : 0.f;
#pragma unroll
        for (int o = 4; o > 0; o >>= 1) t += __shfl_xor_sync(0xffffffffu, t, o);
        if (lane == 0) stat[0] = t;
    }
    __syncthreads();
    const float mean = stat[0] * (1.f / 1024.f);

    const float dx = v.x - mean, dy = v.y - mean, dz = v.z - mean, dw = v.w - mean;
    float ss = dx * dx + dy * dy + dz * dz + dw * dw;
#pragma unroll
    for (int o = 16; o > 0; o >>= 1) ss += __shfl_xor_sync(0xffffffffu, ss, o);
    __syncthreads();
    if (lane == 0) sh[wid] = ss;
    __syncthreads();
    if (wid == 0) {
        float t = (lane < 8) ? sh[lane] : 0.f;
#pragma unroll
        for (int o = 4; o > 0; o >>= 1) t += __shfl_xor_sync(0xffffffffu, t, o);
        if (lane == 0) stat[1] = t;
    }
    __syncthreads();
    const float inv = rsqrtf(stat[1] * (1.f / 1024.f) + 1e-5f);

    const float4 gg = ((const float4*)g)[tid];
    const float4 bb = ((const float4*)bt)[tid];
    float4 o4;
    o4.x = tf32r(dx * inv * gg.x + bb.x);
    o4.y = tf32r(dy * inv * gg.y + bb.y);
    o4.z = tf32r(dz * inv * gg.z + bb.z);
    o4.w = tf32r(dw * inv * gg.w + bb.w);
    ((float4*)row)[tid] = o4;
}

// ---------------- row softmax over length-1024 rows (in place, tf32-rounded out) ----------------
__global__ __launch_bounds__(256)
void softmax_k(float* __restrict__ p)
{
    __shared__ float sh[8];
    __shared__ float stat[2];
    float* row = p + (long long)blockIdx.x * 1024;
    const int tid  = threadIdx.x;
    const int lane = tid & 31;
    const int wid  = tid >> 5;

    float4 v = ((const float4*)row)[tid];
    float mx = fmaxf(fmaxf(v.x, v.y), fmaxf(v.z, v.w));
#pragma unroll
    for (int o = 16; o > 0; o >>= 1)
        mx = fmaxf(mx, __shfl_xor_sync(0xffffffffu, mx, o));
    if (lane == 0) sh[wid] = mx;
    __syncthreads();
    if (wid == 0) {
        float t = (lane < 8) ? sh[lane] : -3.4e38f;
#pragma unroll
        for (int o = 4; o > 0; o >>= 1)
            t = fmaxf(t, __shfl_xor_sync(0xffffffffu, t, o));
        if (lane == 0) stat[0] = t;
    }
    __syncthreads();
    const float m = stat[0];

    v.x = __expf(v.x - m);
    v.y = __expf(v.y - m);
    v.z = __expf(v.z - m);
    v.w = __expf(v.w - m);
    float s = v.x + v.y + v.z + v.w;
#pragma unroll
    for (int o = 16; o > 0; o >>= 1) s += __shfl_xor_sync(0xffffffffu, s, o);
    __syncthreads();
    if (lane == 0) sh[wid] = s;
    __syncthreads();
    if (wid == 0) {
        float t = (lane < 8) ? sh[lane] : 0.f;
#pragma unroll
        for (int o = 4; o > 0; o >>= 1) t += __shfl_xor_sync(0xffffffffu, t, o);
        if (lane == 0) stat[1] = t;
    }
    __syncthreads();
    const float inv = 1.f / stat[1];
    float4 o4;
    o4.x = tf32r(v.x * inv);
    o4.y = tf32r(v.y * inv);
    o4.z = tf32r(v.z * inv);
    o4.w = tf32r(v.w * inv);
    ((float4*)row)[tid] = o4;
}

// ---------------- tiled transpose: out[c, r] = in[r, c] (optional tf32 round) ----------------
__global__ __launch_bounds__(256)
void transpose_k(const float* __restrict__ in, int ldi, long long sIn,
                 float* __restrict__ out, int ldo, long long sOut, int rnd)
{
    __shared__ float t[32][33];
    in  += (long long)blockIdx.z * sIn;
    out += (long long)blockIdx.z * sOut;
    const int r0 = blockIdx.y * 32;
    const int c0 = blockIdx.x * 32;
    const int x = threadIdx.x;   // 32
    const int y = threadIdx.y;   // 8
#pragma unroll
    for (int i = 0; i < 32; i += 8)
        t[y + i][x] = in[(long long)(r0 + y + i) * ldi + c0 + x];
    __syncthreads();
    if (rnd) {
#pragma unroll
        for (int i = 0; i < 32; i += 8)
            out[(long long)(c0 + y + i) * ldo + r0 + x] = tf32r(t[x][y + i]);
    } else {
#pragma unroll
        for (int i = 0; i < 32; i += 8)
            out[(long long)(c0 + y + i) * ldo + r0 + x] = t[x][y + i];
    }
}

// ---------------- launcher ----------------
extern "C" void kernel_launch(void* const* d_in, const int* in_sizes, int n_in,
                              void* d_out, int out_size)
{
    const float* x_spa  = (const float*)d_in[0];
    const float* x_freq = (const float*)d_in[1];
    const float* w_cdc  = (const float*)d_in[2];
    const float* b_cdc  = (const float*)d_in[3];
    const float* w_sv   = (const float*)d_in[4];
    const float* b_sv   = (const float*)d_in[5];
    const float* w_fv   = (const float*)d_in[6];
    const float* b_fv   = (const float*)d_in[7];
    const float* ln_w   = (const float*)d_in[8];
    const float* ln_b   = (const float*)d_in[9];
    const float* w_qk   = (const float*)d_in[10];
    const float* w_spa  = (const float*)d_in[11];
    const float* b_spa  = (const float*)d_in[12];
    const float* w_frq  = (const float*)d_in[13];
    const float* b_frq  = (const float*)d_in[14];

    float* out_spa  = (float*)d_out;
    float* out_freq = (float*)d_out + (long long)NB * NC * HW;

    float *p_x, *p_vspa, *p_vfreq, *p_qk, *p_qT, *p_att, *p_p;
    float *p_wqkT, *p_wspaT, *p_wfrqT;
    float *p_xspar, *p_xfreqr, *p_wcdcr, *p_wsvr, *p_wfvr;
    cudaGetSymbolAddress((void**)&p_x,      g_x);
    cudaGetSymbolAddress((void**)&p_vspa,   g_vspa);
    cudaGetSymbolAddress((void**)&p_vfreq,  g_vfreq);
    cudaGetSymbolAddress((void**)&p_qk,     g_qk);
    cudaGetSymbolAddress((void**)&p_qT,     g_qT);
    cudaGetSymbolAddress((void**)&p_att,    g_att);
    cudaGetSymbolAddress((void**)&p_p,      g_p);
    cudaGetSymbolAddress((void**)&p_wqkT,   g_wqkT);
    cudaGetSymbolAddress((void**)&p_wspaT,  g_wspaT);
    cudaGetSymbolAddress((void**)&p_wfrqT,  g_wfrqT);
    cudaGetSymbolAddress((void**)&p_xspar,  g_xspar);
    cudaGetSymbolAddress((void**)&p_xfreqr, g_xfreqr);
    cudaGetSymbolAddress((void**)&p_wcdcr,  g_wcdcr);
    cudaGetSymbolAddress((void**)&p_wsvr,   g_wsvr);
    cudaGetSymbolAddress((void**)&p_wfvr,   g_wfvr);

    static int smem_set = 0;
    if (!smem_set) {
        cudaFuncSetAttribute(sgemm_tc, cudaFuncAttributeMaxDynamicSharedMemorySize, SMEM_BYTES);
        smem_set = 1;
    }

    const long long sX   = (long long)NC * HW;        // 262144
    const long long sQK  = (long long)NC * 2 * HW;    // 524288
    const long long sQT  = (long long)HW * NC;        // 262144
    const long long sAtt = (long long)HW * HW;        // 1048576
    const dim3 tb(32, 8);
    const float scale = 0.03125f;                     // hw^-0.5 = 1/32

    // tf32-round raw inputs & conv weights (launch indices 0..4)
    round_k<<<(NB * NC * HW / 4 + 255) / 256, 256>>>((const float4*)x_spa,  (float4*)p_xspar,  NB * NC * HW / 4);
    round_k<<<(NB * NC * HW / 4 + 255) / 256, 256>>>((const float4*)x_freq, (float4*)p_xfreqr, NB * NC * HW / 4);
    round_k<<<(NC * 2 * NC / 4 + 255) / 256, 256>>>((const float4*)w_cdc, (float4*)p_wcdcr, NC * 2 * NC / 4);
    round_k<<<(NC * NC / 4 + 255) / 256, 256>>>((const float4*)w_sv, (float4*)p_wsvr, NC * NC / 4);
    round_k<<<(NC * NC / 4 + 255) / 256, 256>>>((const float4*)w_fv, (float4*)p_wfvr, NC * NC / 4);

    // launch index 5 == first GEMM (ncu -s 5 profiles this)
    // X = w_cdc[:, :256] @ x_spa + b_cdc
    sgemm_tc<<<dim3(HW / BN, NC / BM, NB), 128, SMEM_BYTES>>>(
        p_wcdcr, 512, 0, p_xspar, 1024, sX, nullptr, 0, b_cdc, nullptr,
        p_x, 1024, sX, 256, 1.f, 0);
    // X += w_cdc[:, 256:] @ x_freq
    sgemm_tc<<<dim3(HW / BN, NC / BM, NB), 128, SMEM_BYTES>>>(
        p_wcdcr + 256, 512, 0, p_xfreqr, 1024, sX, p_x, sX, nullptr, nullptr,
        p_x, 1024, sX, 256, 1.f, 0);

    // v_spa / v_freq (rounded outputs for final GEMM)
    sgemm_tc<<<dim3(HW / BN, NC / BM, NB), 128, SMEM_BYTES>>>(
        p_wsvr, 256, 0, p_xspar, 1024, sX, nullptr, 0, b_sv, nullptr,
        p_vspa, 1024, sX, 256, 1.f, 1);
    sgemm_tc<<<dim3(HW / BN, NC / BM, NB), 128, SMEM_BYTES>>>(
        p_wfvr, 256, 0, p_xfreqr, 1024, sX, nullptr, 0, b_fv, nullptr,
        p_vfreq, 1024, sX, 256, 1.f, 1);

    // weight transposes (rounded)
    transpose_k<<<dim3(1024 / 32, 2048 / 32, 1), tb>>>(w_qk, 1024, 0, p_wqkT, 2048, 0, 1);
    transpose_k<<<dim3(1024 / 32, 1024 / 32, 1), tb>>>(w_spa, 1024, 0, p_wspaT, 1024, 0, 1);
    transpose_k<<<dim3(1024 / 32, 1024 / 32, 1), tb>>>(w_frq, 1024, 0, p_wfrqT, 1024, 0, 1);

    // LayerNorm rows of X (writes tf32-rounded)
    layernorm_k<<<NB * NC, 256>>>(p_x, ln_w, ln_b);

    // qk = X @ w_qk^T   [256, 2048] (rounded)
    sgemm_tc<<<dim3(2048 / BN, NC / BM, NB), 128, SMEM_BYTES>>>(
        p_x, 1024, sX, p_wqkT, 2048, 0, nullptr, 0, nullptr, nullptr,
        p_qk, 2048, sQK, 1024, 1.f, 1);

    // qT[b][n][c] = q[b][c][n] (already rounded)
    transpose_k<<<dim3(HW / 32, NC / 32, NB), tb>>>(p_qk, 2048, sQK, p_qT, 256, sQT, 0);

    // att = (qT @ k) * scale   [1024, 1024], K = 256 (rounded)
    sgemm_tc<<<dim3(HW / BN, HW / BM, NB), 128, SMEM_BYTES>>>(
        p_qT, 256, sQT, p_qk + 1024, 2048, sQK, nullptr, 0, nullptr, nullptr,
        p_att, 1024, sAtt, 256, scale, 1);

    // ---- spatial branch ----
    sgemm_tc<<<dim3(HW / BN, HW / BM, NB), 128, SMEM_BYTES>>>(
        p_att, 1024, sAtt, p_wspaT, 1024, 0, nullptr, 0, nullptr, b_spa,
        p_p, 1024, sAtt, 1024, 1.f, 0);
    softmax_k<<<NB * HW, 256>>>(p_p);
    sgemm_tc<<<dim3(HW / BN, NC / BM, NB), 128, SMEM_BYTES>>>(
        p_vspa, 1024, sX, p_p, 1024, sAtt, x_spa, sX, nullptr, nullptr,
        out_spa, 1024, sX, 1024, 1.f, 0);

    // ---- frequency branch (reuses g_p) ----
    sgemm_tc<<<dim3(HW / BN, HW / BM, NB), 128, SMEM_BYTES>>>(
        p_att, 1024, sAtt, p_wfrqT, 1024, 0, nullptr, 0, nullptr, b_frq,
        p_p, 1024, sAtt, 1024, 1.f, 0);
    softmax_k<<<NB * HW, 256>>>(p_p);
    sgemm_tc<<<dim3(HW / BN, NC / BM, NB), 128, SMEM_BYTES>>>(
        p_vfreq, 1024, sX, p_p, 1024, sAtt, x_freq, sX, nullptr, nullptr,
        out_freq, 1024, sX, 1024, 1.f, 0);

    (void)in_sizes; (void)n_in; (void)out_size;
}

// round 6
// speedup vs baseline: 4.6022x; 1.3467x over previous
#include <cuda_runtime.h>
#include <cstdint>

// ---------------- problem constants ----------------
#define NB   16
#define NC   256
#define HW   1024
#define DIM  1024

// ---------------- scratch (device globals; no allocation) ----------------
__device__ float g_x[NB * NC * HW];            // cdc output, then LN'd (tf32-rounded)
__device__ float g_vspa[NB * NC * HW];
__device__ float g_vfreq[NB * NC * HW];
__device__ float g_qk[NB * NC * 2 * HW];       // [b, c, 2048]: q | k
__device__ float g_qT[NB * HW * NC];           // [b, n, c]
__device__ float g_kw[2 * NB * NC * HW];       // kw_spa | kw_freq  [b, c, o], rounded
__device__ float g_p[NB * HW * HW];            // logits -> softmax probs (reused)
__device__ float g_wqkT[DIM * 2 * DIM];
__device__ float g_wspaT[DIM * DIM];
__device__ float g_wfrqT[DIM * DIM];
__device__ float g_xspar[NB * NC * HW];        // tf32-rounded copies of inputs
__device__ float g_xfreqr[NB * NC * HW];
__device__ float g_wcdcr[NC * 2 * NC];
__device__ float g_wsvr[NC * NC];
__device__ float g_wfvr[NC * NC];

// ---------------- helpers ----------------
__device__ __forceinline__ float tf32r(float x) {
    asm("cvt.rna.tf32.f32 %0, %1;" : "=f"(x) : "f"(x));
    return x;
}
__device__ __forceinline__ void cpasync16(uint32_t dst, const void* src) {
    asm volatile("cp.async.cg.shared.global [%0], [%1], 16;\n" :: "r"(dst), "l"(src));
}
__device__ __forceinline__ void cpcommit() {
    asm volatile("cp.async.commit_group;\n");
}
__device__ __forceinline__ void cpwait1() {
    asm volatile("cp.async.wait_group 1;\n");
}
__device__ __forceinline__ void cpwait0() {
    asm volatile("cp.async.wait_group 0;\n");
}
__device__ __forceinline__ void mma_tf32(float* d, const uint32_t* a, const uint32_t* b) {
    asm volatile(
        "mma.sync.aligned.m16n8k8.row.col.f32.tf32.tf32.f32 "
        "{%0,%1,%2,%3}, {%4,%5,%6,%7}, {%8,%9}, {%0,%1,%2,%3};\n"
        : "+f"(d[0]), "+f"(d[1]), "+f"(d[2]), "+f"(d[3])
        : "r"(a[0]), "r"(a[1]), "r"(a[2]), "r"(a[3]), "r"(b[0]), "r"(b[1]));
}

// ---------------- tf32 tensor-core GEMM ----------------
// C[m,n] = alpha*sum_k A[m,k]*B[k,n] + biasRow[m] + biasCol[n] + Add[m,n]
// Operands A,B MUST already be tf32-rounded fp32. M%128==0, N%128==0, K%32==0.
// 128 threads (4 warps, 2x2), warp tile 64x64, CTA tile 128x128x32, 3-stage cp.async.
#define BM 128
#define BN 128
#define BKT 32
#define AS_LD 36            // floats per A row in smem (pad 4): bank = 4m+k, conflict-free
#define BS_LD 136           // floats per B row in smem (pad 8): bank = 8k+n, conflict-free
#define AS_FLOATS (BM * AS_LD)            // 4608
#define BS_FLOATS (BKT * BS_LD)           // 4352
#define STAGE_FLOATS (AS_FLOATS + BS_FLOATS)   // 8960
#define STAGE_BYTES (STAGE_FLOATS * 4)         // 35840
#define NSTAGES 3
#define SMEM_BYTES (STAGE_BYTES * NSTAGES)     // 107520 -> 2 CTAs/SM

__global__ __launch_bounds__(128, 2)
void sgemm_tc(const float* __restrict__ A, int lda, long long sA,
              const float* __restrict__ B, int ldb, long long sB,
              const float* __restrict__ Add, long long sAdd,
              const float* __restrict__ biasRow, const float* __restrict__ biasCol,
              float* __restrict__ C, int ldc, long long sC,
              int K, float alpha, int roundC)
{
    extern __shared__ float smem[];
    const uint32_t smem_u32 = (uint32_t)__cvta_generic_to_shared(smem);

    const long long bz = blockIdx.z;
    A += bz * sA;
    B += bz * sB;
    C += bz * sC;
    if (Add) Add += bz * sAdd;

    const int bm = blockIdx.y * BM;
    const int bn = blockIdx.x * BN;
    const int tid  = threadIdx.x;
    const int lane = tid & 31;
    const int wid  = tid >> 5;
    const int wm = wid >> 1;     // 0..1
    const int wn = wid & 1;      // 0..1
    const int rb = wm * 64;
    const int cb = wn * 64;
    const int lr = lane >> 2;    // 0..7
    const int lc = lane & 3;     // 0..3

    float acc[4][8][4];
#pragma unroll
    for (int i = 0; i < 4; i++)
#pragma unroll
        for (int j = 0; j < 8; j++)
#pragma unroll
            for (int v = 0; v < 4; v++) acc[i][j][v] = 0.f;

    const int a_row = tid >> 3;           // 0..15 (plus +16*u)
    const int a_k4  = (tid & 7) * 4;
    const int b_row = tid >> 5;           // 0..3 (plus +4*u)
    const int b_n4  = (tid & 31) * 4;

    const int T = K / BKT;

    auto load_stage = [&](int t, int s) {
        const int k0 = t * BKT;
        const uint32_t sa = smem_u32 + s * STAGE_BYTES;
        const uint32_t sb = sa + AS_FLOATS * 4;
#pragma unroll
        for (int u = 0; u < 8; u++) {
            const int r = a_row + u * 16;
            cpasync16(sa + (r * AS_LD + a_k4) * 4,
                      A + (long long)(bm + r) * lda + k0 + a_k4);
        }
#pragma unroll
        for (int u = 0; u < 8; u++) {
            const int r = b_row + u * 4;
            cpasync16(sb + (r * BS_LD + b_n4) * 4,
                      B + (long long)(k0 + r) * ldb + bn + b_n4);
        }
    };

    load_stage(0, 0); cpcommit();
    if (T > 1) { load_stage(1, 1); cpcommit(); }

    for (int t = 0; t < T; t++) {
        if (t < T - 1) cpwait1(); else cpwait0();
        __syncthreads();
        if (t + 2 < T) { load_stage(t + 2, (t + 2) % NSTAGES); }
        cpcommit();

        const float* sA_ = smem + (t % NSTAGES) * STAGE_FLOATS;
        const float* sB_ = sA_ + AS_FLOATS;

#pragma unroll
        for (int kk = 0; kk < 4; kk++) {
            const int kb = kk * 8 + lc;
            uint32_t a[4][4];
#pragma unroll
            for (int mi = 0; mi < 4; mi++) {
                const int m0 = rb + mi * 16 + lr;
                a[mi][0] = __float_as_uint(sA_[m0 * AS_LD + kb]);
                a[mi][1] = __float_as_uint(sA_[(m0 + 8) * AS_LD + kb]);
                a[mi][2] = __float_as_uint(sA_[m0 * AS_LD + kb + 4]);
                a[mi][3] = __float_as_uint(sA_[(m0 + 8) * AS_LD + kb + 4]);
            }
            uint32_t b[8][2];
#pragma unroll
            for (int ni = 0; ni < 8; ni++) {
                const int n0 = cb + ni * 8 + lr;
                b[ni][0] = __float_as_uint(sB_[kb * BS_LD + n0]);
                b[ni][1] = __float_as_uint(sB_[(kb + 4) * BS_LD + n0]);
            }
#pragma unroll
            for (int mi = 0; mi < 4; mi++)
#pragma unroll
                for (int ni = 0; ni < 8; ni++)
                    mma_tf32(acc[mi][ni], a[mi], b[ni]);
        }
        __syncthreads();
    }

    // epilogue
#pragma unroll
    for (int mi = 0; mi < 4; mi++) {
#pragma unroll
        for (int half = 0; half < 2; half++) {
            const int r = bm + rb + mi * 16 + lr + half * 8;
            const float br = biasRow ? biasRow[r] : 0.f;
            const long long rowoff = (long long)r * ldc;
#pragma unroll
            for (int ni = 0; ni < 8; ni++) {
                const int c = bn + cb + ni * 8 + lc * 2;
                float f0 = alpha * acc[mi][ni][half * 2 + 0] + br;
                float f1 = alpha * acc[mi][ni][half * 2 + 1] + br;
                if (biasCol) {
                    const float2 bc = *(const float2*)(biasCol + c);
                    f0 += bc.x; f1 += bc.y;
                }
                if (Add) {
                    const float2 ad = *(const float2*)(Add + rowoff + c);
                    f0 += ad.x; f1 += ad.y;
                }
                if (roundC) { f0 = tf32r(f0); f1 = tf32r(f1); }
                float2 o; o.x = f0; o.y = f1;
                *(float2*)(C + rowoff + c) = o;
            }
        }
    }
}

// ---------------- tf32 rounding pass ----------------
__global__ __launch_bounds__(256)
void round_k(const float4* __restrict__ in, float4* __restrict__ out, int n4)
{
    int i = blockIdx.x * 256 + threadIdx.x;
    if (i < n4) {
        float4 v = in[i];
        v.x = tf32r(v.x); v.y = tf32r(v.y); v.z = tf32r(v.z); v.w = tf32r(v.w);
        out[i] = v;
    }
}

// ---------------- LayerNorm over rows of length 1024 (in place, tf32-rounded out) ----------------
__global__ __launch_bounds__(256)
void layernorm_k(float* __restrict__ x, const float* __restrict__ g,
                 const float* __restrict__ bt)
{
    __shared__ float sh[8];
    __shared__ float stat[2];
    float* row = x + (long long)blockIdx.x * 1024;
    const int tid  = threadIdx.x;
    const int lane = tid & 31;
    const int wid  = tid >> 5;

    float4 v = ((const float4*)row)[tid];

    float s = v.x + v.y + v.z + v.w;
#pragma unroll
    for (int o = 16; o > 0; o >>= 1) s += __shfl_xor_sync(0xffffffffu, s, o);
    if (lane == 0) sh[wid] = s;
    __syncthreads();
    if (wid == 0) {
        float t = (lane < 8) ? sh[lane] : 0.f;
#pragma unroll
        for (int o = 4; o > 0; o >>= 1) t += __shfl_xor_sync(0xffffffffu, t, o);
        if (lane == 0) stat[0] = t;
    }
    __syncthreads();
    const float mean = stat[0] * (1.f / 1024.f);

    const float dx = v.x - mean, dy = v.y - mean, dz = v.z - mean, dw = v.w - mean;
    float ss = dx * dx + dy * dy + dz * dz + dw * dw;
#pragma unroll
    for (int o = 16; o > 0; o >>= 1) ss += __shfl_xor_sync(0xffffffffu, ss, o);
    __syncthreads();
    if (lane == 0) sh[wid] = ss;
    __syncthreads();
    if (wid == 0) {
        float t = (lane < 8) ? sh[lane] : 0.f;
#pragma unroll
        for (int o = 4; o > 0; o >>= 1) t += __shfl_xor_sync(0xffffffffu, t, o);
        if (lane == 0) stat[1] = t;
    }
    __syncthreads();
    const float inv = rsqrtf(stat[1] * (1.f / 1024.f) + 1e-5f);

    const float4 gg = ((const float4*)g)[tid];
    const float4 bb = ((const float4*)bt)[tid];
    float4 o4;
    o4.x = tf32r(dx * inv * gg.x + bb.x);
    o4.y = tf32r(dy * inv * gg.y + bb.y);
    o4.z = tf32r(dz * inv * gg.z + bb.z);
    o4.w = tf32r(dw * inv * gg.w + bb.w);
    ((float4*)row)[tid] = o4;
}

// ---------------- row softmax over length-1024 rows (in place, tf32-rounded out) ----------------
__global__ __launch_bounds__(256)
void softmax_k(float* __restrict__ p)
{
    __shared__ float sh[8];
    __shared__ float stat[2];
    float* row = p + (long long)blockIdx.x * 1024;
    const int tid  = threadIdx.x;
    const int lane = tid & 31;
    const int wid  = tid >> 5;

    float4 v = ((const float4*)row)[tid];
    float mx = fmaxf(fmaxf(v.x, v.y), fmaxf(v.z, v.w));
#pragma unroll
    for (int o = 16; o > 0; o >>= 1)
        mx = fmaxf(mx, __shfl_xor_sync(0xffffffffu, mx, o));
    if (lane == 0) sh[wid] = mx;
    __syncthreads();
    if (wid == 0) {
        float t = (lane < 8) ? sh[lane] : -3.4e38f;
#pragma unroll
        for (int o = 4; o > 0; o >>= 1)
            t = fmaxf(t, __shfl_xor_sync(0xffffffffu, t, o));
        if (lane == 0) stat[0] = t;
    }
    __syncthreads();
    const float m = stat[0];

    v.x = __expf(v.x - m);
    v.y = __expf(v.y - m);
    v.z = __expf(v.z - m);
    v.w = __expf(v.w - m);
    float s = v.x + v.y + v.z + v.w;
#pragma unroll
    for (int o = 16; o > 0; o >>= 1) s += __shfl_xor_sync(0xffffffffu, s, o);
    __syncthreads();
    if (lane == 0) sh[wid] = s;
    __syncthreads();
    if (wid == 0) {
        float t = (lane < 8) ? sh[lane] : 0.f;
#pragma unroll
        for (int o = 4; o > 0; o >>= 1) t += __shfl_xor_sync(0xffffffffu, t, o);
        if (lane == 0) stat[1] = t;
    }
    __syncthreads();
    const float inv = 1.f / stat[1];
    float4 o4;
    o4.x = tf32r(v.x * inv);
    o4.y = tf32r(v.y * inv);
    o4.z = tf32r(v.z * inv);
    o4.w = tf32r(v.w * inv);
    ((float4*)row)[tid] = o4;
}

// ---------------- tiled transpose: out[c, r] = in[r, c] (optional tf32 round) ----------------
__global__ __launch_bounds__(256)
void transpose_k(const float* __restrict__ in, int ldi, long long sIn,
                 float* __restrict__ out, int ldo, long long sOut, int rnd)
{
    __shared__ float t[32][33];
    in  += (long long)blockIdx.z * sIn;
    out += (long long)blockIdx.z * sOut;
    const int r0 = blockIdx.y * 32;
    const int c0 = blockIdx.x * 32;
    const int x = threadIdx.x;   // 32
    const int y = threadIdx.y;   // 8
#pragma unroll
    for (int i = 0; i < 32; i += 8)
        t[y + i][x] = in[(long long)(r0 + y + i) * ldi + c0 + x];
    __syncthreads();
    if (rnd) {
#pragma unroll
        for (int i = 0; i < 32; i += 8)
            out[(long long)(c0 + y + i) * ldo + r0 + x] = tf32r(t[x][y + i]);
    } else {
#pragma unroll
        for (int i = 0; i < 32; i += 8)
            out[(long long)(c0 + y + i) * ldo + r0 + x] = t[x][y + i];
    }
}

// ---------------- launcher ----------------
extern "C" void kernel_launch(void* const* d_in, const int* in_sizes, int n_in,
                              void* d_out, int out_size)
{
    const float* x_spa  = (const float*)d_in[0];
    const float* x_freq = (const float*)d_in[1];
    const float* w_cdc  = (const float*)d_in[2];
    const float* b_cdc  = (const float*)d_in[3];
    const float* w_sv   = (const float*)d_in[4];
    const float* b_sv   = (const float*)d_in[5];
    const float* w_fv   = (const float*)d_in[6];
    const float* b_fv   = (const float*)d_in[7];
    const float* ln_w   = (const float*)d_in[8];
    const float* ln_b   = (const float*)d_in[9];
    const float* w_qk   = (const float*)d_in[10];
    const float* w_spa  = (const float*)d_in[11];
    const float* b_spa  = (const float*)d_in[12];
    const float* w_frq  = (const float*)d_in[13];
    const float* b_frq  = (const float*)d_in[14];

    float* out_spa  = (float*)d_out;
    float* out_freq = (float*)d_out + (long long)NB * NC * HW;

    float *p_x, *p_vspa, *p_vfreq, *p_qk, *p_qT, *p_kw, *p_p;
    float *p_wqkT, *p_wspaT, *p_wfrqT;
    float *p_xspar, *p_xfreqr, *p_wcdcr, *p_wsvr, *p_wfvr;
    cudaGetSymbolAddress((void**)&p_x,      g_x);
    cudaGetSymbolAddress((void**)&p_vspa,   g_vspa);
    cudaGetSymbolAddress((void**)&p_vfreq,  g_vfreq);
    cudaGetSymbolAddress((void**)&p_qk,     g_qk);
    cudaGetSymbolAddress((void**)&p_qT,     g_qT);
    cudaGetSymbolAddress((void**)&p_kw,     g_kw);
    cudaGetSymbolAddress((void**)&p_p,      g_p);
    cudaGetSymbolAddress((void**)&p_wqkT,   g_wqkT);
    cudaGetSymbolAddress((void**)&p_wspaT,  g_wspaT);
    cudaGetSymbolAddress((void**)&p_wfrqT,  g_wfrqT);
    cudaGetSymbolAddress((void**)&p_xspar,  g_xspar);
    cudaGetSymbolAddress((void**)&p_xfreqr, g_xfreqr);
    cudaGetSymbolAddress((void**)&p_wcdcr,  g_wcdcr);
    cudaGetSymbolAddress((void**)&p_wsvr,   g_wsvr);
    cudaGetSymbolAddress((void**)&p_wfvr,   g_wfvr);

    static int smem_set = 0;
    if (!smem_set) {
        cudaFuncSetAttribute(sgemm_tc, cudaFuncAttributeMaxDynamicSharedMemorySize, SMEM_BYTES);
        smem_set = 1;
    }

    const long long sX   = (long long)NC * HW;        // 262144
    const long long sQK  = (long long)NC * 2 * HW;    // 524288
    const long long sQT  = (long long)HW * NC;        // 262144
    const long long sKW  = (long long)NC * HW;        // 262144
    const long long sAtt = (long long)HW * HW;        // 1048576
    float* p_kwspa  = p_kw;
    float* p_kwfreq = p_kw + (long long)NB * NC * HW;
    const dim3 tb(32, 8);
    const float scale = 0.03125f;                     // hw^-0.5 = 1/32

    // rounds (launch idx 0..3)
    round_k<<<(NB * NC * HW / 4 + 255) / 256, 256>>>((const float4*)x_spa,  (float4*)p_xspar,  NB * NC * HW / 4);
    round_k<<<(NB * NC * HW / 4 + 255) / 256, 256>>>((const float4*)x_freq, (float4*)p_xfreqr, NB * NC * HW / 4);
    round_k<<<(NC * 2 * NC / 4 + 255) / 256, 256>>>((const float4*)w_cdc, (float4*)p_wcdcr, NC * 2 * NC / 4);
    round_k<<<(NC * NC / 4 + 255) / 256, 256>>>((const float4*)w_sv, (float4*)p_wsvr, NC * NC / 4);

    // GEMMs at idx 4..6 (ncu -s 5 lands on a GEMM)
    sgemm_tc<<<dim3(HW / BN, NC / BM, NB), 128, SMEM_BYTES>>>(       // idx 4: cdc part 1
        p_wcdcr, 512, 0, p_xspar, 1024, sX, nullptr, 0, b_cdc, nullptr,
        p_x, 1024, sX, 256, 1.f, 0);
    sgemm_tc<<<dim3(HW / BN, NC / BM, NB), 128, SMEM_BYTES>>>(       // idx 5: cdc part 2
        p_wcdcr + 256, 512, 0, p_xfreqr, 1024, sX, p_x, sX, nullptr, nullptr,
        p_x, 1024, sX, 256, 1.f, 0);
    sgemm_tc<<<dim3(HW / BN, NC / BM, NB), 128, SMEM_BYTES>>>(       // idx 6: v_spa
        p_wsvr, 256, 0, p_xspar, 1024, sX, nullptr, 0, b_sv, nullptr,
        p_vspa, 1024, sX, 256, 1.f, 1);

    round_k<<<(NC * NC / 4 + 255) / 256, 256>>>((const float4*)w_fv, (float4*)p_wfvr, NC * NC / 4);
    sgemm_tc<<<dim3(HW / BN, NC / BM, NB), 128, SMEM_BYTES>>>(       // v_freq
        p_wfvr, 256, 0, p_xfreqr, 1024, sX, nullptr, 0, b_fv, nullptr,
        p_vfreq, 1024, sX, 256, 1.f, 1);

    // weight transposes (rounded)
    transpose_k<<<dim3(1024 / 32, 2048 / 32, 1), tb>>>(w_qk, 1024, 0, p_wqkT, 2048, 0, 1);
    transpose_k<<<dim3(1024 / 32, 1024 / 32, 1), tb>>>(w_spa, 1024, 0, p_wspaT, 1024, 0, 1);
    transpose_k<<<dim3(1024 / 32, 1024 / 32, 1), tb>>>(w_frq, 1024, 0, p_wfrqT, 1024, 0, 1);

    // LayerNorm rows of X (writes tf32-rounded)
    layernorm_k<<<NB * NC, 256>>>(p_x, ln_w, ln_b);

    // qk = X @ w_qk^T   [256, 2048] (rounded)
    sgemm_tc<<<dim3(2048 / BN, NC / BM, NB), 128, SMEM_BYTES>>>(
        p_x, 1024, sX, p_wqkT, 2048, 0, nullptr, 0, nullptr, nullptr,
        p_qk, 2048, sQK, 1024, 1.f, 1);

    // qT[b][n][c] = q[b][c][n] (already rounded)
    transpose_k<<<dim3(HW / 32, NC / 32, NB), tb>>>(p_qk, 2048, sQK, p_qT, 256, sQT, 0);

    // kw_spa = k @ w_spa^T   [256, 1024], K = 1024 (rounded)
    sgemm_tc<<<dim3(HW / BN, NC / BM, NB), 128, SMEM_BYTES>>>(
        p_qk + 1024, 2048, sQK, p_wspaT, 1024, 0, nullptr, 0, nullptr, nullptr,
        p_kwspa, 1024, sKW, 1024, 1.f, 1);
    // kw_freq = k @ w_frq^T
    sgemm_tc<<<dim3(HW / BN, NC / BM, NB), 128, SMEM_BYTES>>>(
        p_qk + 1024, 2048, sQK, p_wfrqT, 1024, 0, nullptr, 0, nullptr, nullptr,
        p_kwfreq, 1024, sKW, 1024, 1.f, 1);

    // ---- spatial branch ----
    // logits = scale * qT @ kw_spa + b_spa   [1024, 1024], K = 256
    sgemm_tc<<<dim3(HW / BN, HW / BM, NB), 128, SMEM_BYTES>>>(
        p_qT, 256, sQT, p_kwspa, 1024, sKW, nullptr, 0, nullptr, b_spa,
        p_p, 1024, sAtt, 256, scale, 0);
    softmax_k<<<NB * HW, 256>>>(p_p);
    sgemm_tc<<<dim3(HW / BN, NC / BM, NB), 128, SMEM_BYTES>>>(
        p_vspa, 1024, sX, p_p, 1024, sAtt, x_spa, sX, nullptr, nullptr,
        out_spa, 1024, sX, 1024, 1.f, 0);

    // ---- frequency branch (reuses g_p) ----
    sgemm_tc<<<dim3(HW / BN, HW / BM, NB), 128, SMEM_BYTES>>>(
        p_qT, 256, sQT, p_kwfreq, 1024, sKW, nullptr, 0, nullptr, b_frq,
        p_p, 1024, sAtt, 256, scale, 0);
    softmax_k<<<NB * HW, 256>>>(p_p);
    sgemm_tc<<<dim3(HW / BN, NC / BM, NB), 128, SMEM_BYTES>>>(
        p_vfreq, 1024, sX, p_p, 1024, sAtt, x_freq, sX, nullptr, nullptr,
        out_freq, 1024, sX, 1024, 1.f, 0);

    (void)in_sizes; (void)n_in; (void)out_size;
}

// round 10
// speedup vs baseline: 4.7368x; 1.0292x over previous
#include <cuda_runtime.h>
#include <cstdint>

// ---------------- problem constants ----------------
#define NB   16
#define NC   256
#define HW   1024
#define DIM  1024

// ---------------- scratch (device globals; no allocation) ----------------
__device__ float g_x[NB * NC * HW];            // cdc output, then LN'd (tf32-rounded)
__device__ float g_vspa[NB * NC * HW];
__device__ float g_vfreq[NB * NC * HW];
__device__ float g_qk[NB * NC * 2 * HW];       // [b, c, 2048]: q | k
__device__ float g_qT[NB * HW * NC];           // [b, n, c]
__device__ float g_kw[NB * NC * 2 * HW];       // [b, c, 2048]: kw_spa | kw_freq (rounded)
__device__ float g_E[NB * HW * 2 * HW];        // [b, n, 2048]: exp(logits), rounded
__device__ float g_part[NB * 2 * HW * 16];     // deterministic row-sum partials
__device__ float g_inv[NB * 2 * HW];           // 1/rowsum  [b][branch][n]
__device__ float g_bcat[2 * HW];               // b_spa | b_frq
__device__ float g_wqkT[DIM * 2 * DIM];
__device__ float g_wspaT[DIM * DIM];
__device__ float g_wfrqT[DIM * DIM];
__device__ float g_xspar[NB * NC * HW];        // tf32-rounded copies of inputs
__device__ float g_xfreqr[NB * NC * HW];
__device__ float g_wcdcr[NC * 2 * NC];
__device__ float g_wsvr[NC * NC];
__device__ float g_wfvr[NC * NC];

// ---------------- helpers ----------------
__device__ __forceinline__ float tf32r(float x) {
    asm("cvt.rna.tf32.f32 %0, %1;" : "=f"(x) : "f"(x));
    return x;
}
__device__ __forceinline__ void cpasync16(uint32_t dst, const void* src) {
    asm volatile("cp.async.cg.shared.global [%0], [%1], 16;\n" :: "r"(dst), "l"(src));
}
__device__ __forceinline__ void cpcommit() {
    asm volatile("cp.async.commit_group;\n");
}
__device__ __forceinline__ void cpwait1() {
    asm volatile("cp.async.wait_group 1;\n");
}
__device__ __forceinline__ void cpwait0() {
    asm volatile("cp.async.wait_group 0;\n");
}
__device__ __forceinline__ void mma_tf32(float* d, const uint32_t* a, const uint32_t* b) {
    asm volatile(
        "mma.sync.aligned.m16n8k8.row.col.f32.tf32.tf32.f32 "
        "{%0,%1,%2,%3}, {%4,%5,%6,%7}, {%8,%9}, {%0,%1,%2,%3};\n"
        : "+f"(d[0]), "+f"(d[1]), "+f"(d[2]), "+f"(d[3])
        : "r"(a[0]), "r"(a[1]), "r"(a[2]), "r"(a[3]), "r"(b[0]), "r"(b[1]));
}

// ---------------- tf32 tensor-core GEMM ----------------
// C[m,n] = alpha*sum_k A[m,k]*B[k,n] + biasRow[m] + biasCol[n] + Add[m,n]
// Operands A,B MUST already be tf32-rounded fp32. M%128==0, N%128==0, K%32==0.
// Optional: invA (scale A columns k by invA[k], per-batch stride 2048, re-rounded);
//           partials != nullptr -> exp epilogue (softmax numerator + row partials).
#define BM 128
#define BN 128
#define BKT 32
#define AS_LD 36
#define BS_LD 136
#define AS_FLOATS (BM * AS_LD)            // 4608
#define BS_FLOATS (BKT * BS_LD)           // 4352
#define STAGE_FLOATS (AS_FLOATS + BS_FLOATS)   // 8960
#define STAGE_BYTES (STAGE_FLOATS * 4)         // 35840
#define NSTAGES 3
#define SMEM_BYTES (STAGE_BYTES * NSTAGES)     // 107520 -> 2 CTAs/SM

__global__ __launch_bounds__(128, 2)
void sgemm_tc(const float* __restrict__ A, int lda, long long sA,
              const float* __restrict__ B, int ldb, long long sB,
              const float* __restrict__ Add, long long sAdd,
              const float* __restrict__ biasRow, const float* __restrict__ biasCol,
              float* __restrict__ C, int ldc, long long sC,
              int K, float alpha, int roundC,
              const float* __restrict__ invA, float* __restrict__ partials)
{
    extern __shared__ float smem[];
    const uint32_t smem_u32 = (uint32_t)__cvta_generic_to_shared(smem);

    const long long bz = blockIdx.z;
    A += bz * sA;
    B += bz * sB;
    C += bz * sC;
    if (Add) Add += bz * sAdd;
    const float* invA_b = invA ? (invA + bz * 2048) : nullptr;

    const int bm = blockIdx.y * BM;
    const int bn = blockIdx.x * BN;
    const int tid  = threadIdx.x;
    const int lane = tid & 31;
    const int wid  = tid >> 5;
    const int wm = wid >> 1;     // 0..1
    const int wn = wid & 1;      // 0..1
    const int rb = wm * 64;
    const int cb = wn * 64;
    const int lr = lane >> 2;    // 0..7
    const int lc = lane & 3;     // 0..3

    float acc[4][8][4];
#pragma unroll
    for (int i = 0; i < 4; i++)
#pragma unroll
        for (int j = 0; j < 8; j++)
#pragma unroll
            for (int v = 0; v < 4; v++) acc[i][j][v] = 0.f;

    const int a_row = tid >> 3;           // 0..15 (plus +16*u)
    const int a_k4  = (tid & 7) * 4;
    const int b_row = tid >> 5;           // 0..3 (plus +4*u)
    const int b_n4  = (tid & 31) * 4;

    const int T = K / BKT;

    auto load_stage = [&](int t, int s) {
        const int k0 = t * BKT;
        const uint32_t sa = smem_u32 + s * STAGE_BYTES;
        const uint32_t sb = sa + AS_FLOATS * 4;
        if (invA_b == nullptr) {
#pragma unroll
            for (int u = 0; u < 8; u++) {
                const int r = a_row + u * 16;
                cpasync16(sa + (r * AS_LD + a_k4) * 4,
                          A + (long long)(bm + r) * lda + k0 + a_k4);
            }
        } else {
            const float4 iv = *(const float4*)(invA_b + k0 + a_k4);
            float* sdst = smem + (long long)s * STAGE_FLOATS;
#pragma unroll
            for (int u = 0; u < 8; u++) {
                const int r = a_row + u * 16;
                float4 va = *(const float4*)(A + (long long)(bm + r) * lda + k0 + a_k4);
                va.x = tf32r(va.x * iv.x);
                va.y = tf32r(va.y * iv.y);
                va.z = tf32r(va.z * iv.z);
                va.w = tf32r(va.w * iv.w);
                *(float4*)(sdst + r * AS_LD + a_k4) = va;
            }
        }
#pragma unroll
        for (int u = 0; u < 8; u++) {
            const int r = b_row + u * 4;
            cpasync16(sb + (r * BS_LD + b_n4) * 4,
                      B + (long long)(k0 + r) * ldb + bn + b_n4);
        }
    };

    load_stage(0, 0); cpcommit();
    if (T > 1) { load_stage(1, 1); cpcommit(); }

    for (int t = 0; t < T; t++) {
        if (t < T - 1) cpwait1(); else cpwait0();
        __syncthreads();
        if (t + 2 < T) { load_stage(t + 2, (t + 2) % NSTAGES); }
        cpcommit();

        const float* sA_ = smem + (t % NSTAGES) * STAGE_FLOATS;
        const float* sB_ = sA_ + AS_FLOATS;

#pragma unroll
        for (int kk = 0; kk < 4; kk++) {
            const int kb = kk * 8 + lc;
            uint32_t a[4][4];
#pragma unroll
            for (int mi = 0; mi < 4; mi++) {
                const int m0 = rb + mi * 16 + lr;
                a[mi][0] = __float_as_uint(sA_[m0 * AS_LD + kb]);
                a[mi][1] = __float_as_uint(sA_[(m0 + 8) * AS_LD + kb]);
                a[mi][2] = __float_as_uint(sA_[m0 * AS_LD + kb + 4]);
                a[mi][3] = __float_as_uint(sA_[(m0 + 8) * AS_LD + kb + 4]);
            }
            uint32_t b[8][2];
#pragma unroll
            for (int ni = 0; ni < 8; ni++) {
                const int n0 = cb + ni * 8 + lr;
                b[ni][0] = __float_as_uint(sB_[kb * BS_LD + n0]);
                b[ni][1] = __float_as_uint(sB_[(kb + 4) * BS_LD + n0]);
            }
#pragma unroll
            for (int mi = 0; mi < 4; mi++)
#pragma unroll
                for (int ni = 0; ni < 8; ni++)
                    mma_tf32(acc[mi][ni], a[mi], b[ni]);
        }
        __syncthreads();
    }

    if (partials) {
        // ---- exp epilogue: E = tf32r(exp(clamp(alpha*acc + biasCol))) + row partial sums
        const int h = bn >> 10;                       // branch
        const int slot = ((bn & 1023) + cb) >> 6;     // 0..15
#pragma unroll
        for (int mi = 0; mi < 4; mi++) {
#pragma unroll
            for (int half = 0; half < 2; half++) {
                const int r = bm + rb + mi * 16 + lr + half * 8;
                const long long rowoff = (long long)r * ldc;
                float rowsum = 0.f;
#pragma unroll
                for (int ni = 0; ni < 8; ni++) {
                    const int c = bn + cb + ni * 8 + lc * 2;
                    const float2 bc = *(const float2*)(biasCol + c);
                    float f0 = alpha * acc[mi][ni][half * 2 + 0] + bc.x;
                    float f1 = alpha * acc[mi][ni][half * 2 + 1] + bc.y;
                    f0 = fminf(fmaxf(f0, -80.f), 80.f);
                    f1 = fminf(fmaxf(f1, -80.f), 80.f);
                    f0 = tf32r(__expf(f0));
                    f1 = tf32r(__expf(f1));
                    rowsum += f0 + f1;
                    float2 o; o.x = f0; o.y = f1;
                    *(float2*)(C + rowoff + c) = o;
                }
                rowsum += __shfl_xor_sync(0xffffffffu, rowsum, 1);
                rowsum += __shfl_xor_sync(0xffffffffu, rowsum, 2);
                if (lc == 0) {
                    const long long pidx =
                        (((long long)bz * 2048 + h * 1024 + r) << 4) + slot;
                    partials[pidx] = rowsum;
                }
            }
        }
    } else {
#pragma unroll
        for (int mi = 0; mi < 4; mi++) {
#pragma unroll
            for (int half = 0; half < 2; half++) {
                const int r = bm + rb + mi * 16 + lr + half * 8;
                const float br = biasRow ? biasRow[r] : 0.f;
                const long long rowoff = (long long)r * ldc;
#pragma unroll
                for (int ni = 0; ni < 8; ni++) {
                    const int c = bn + cb + ni * 8 + lc * 2;
                    float f0 = alpha * acc[mi][ni][half * 2 + 0] + br;
                    float f1 = alpha * acc[mi][ni][half * 2 + 1] + br;
                    if (biasCol) {
                        const float2 bc = *(const float2*)(biasCol + c);
                        f0 += bc.x; f1 += bc.y;
                    }
                    if (Add) {
                        const float2 ad = *(const float2*)(Add + rowoff + c);
                        f0 += ad.x; f1 += ad.y;
                    }
                    if (roundC) { f0 = tf32r(f0); f1 = tf32r(f1); }
                    float2 o; o.x = f0; o.y = f1;
                    *(float2*)(C + rowoff + c) = o;
                }
            }
        }
    }
}

// ---------------- tf32 rounding pass ----------------
__global__ __launch_bounds__(256)
void round_k(const float4* __restrict__ in, float4* __restrict__ out, int n4)
{
    int i = blockIdx.x * 256 + threadIdx.x;
    if (i < n4) {
        float4 v = in[i];
        v.x = tf32r(v.x); v.y = tf32r(v.y); v.z = tf32r(v.z); v.w = tf32r(v.w);
        out[i] = v;
    }
}

// ---------------- reduce partials -> inverse row sums ----------------
__global__ __launch_bounds__(256)
void inv_k(const float* __restrict__ part, float* __restrict__ inv, int n)
{
    int i = blockIdx.x * 256 + threadIdx.x;
    if (i < n) {
        const float4* p = (const float4*)(part + ((long long)i << 4));
        float4 a = p[0], b = p[1], c = p[2], d = p[3];
        float s = ((a.x + a.y) + (a.z + a.w)) + ((b.x + b.y) + (b.z + b.w))
                + ((c.x + c.y) + (c.z + c.w)) + ((d.x + d.y) + (d.z + d.w));
        inv[i] = 1.f / s;
    }
}

// ---------------- concat biases ----------------
__global__ __launch_bounds__(256)
void bcat_k(const float* __restrict__ b0, const float* __restrict__ b1,
            float* __restrict__ out)
{
    int i = blockIdx.x * 256 + threadIdx.x;
    if (i < 2048) out[i] = (i < 1024) ? b0[i] : b1[i - 1024];
}

// ---------------- LayerNorm over rows of length 1024 (in place, tf32-rounded out) ----------------
__global__ __launch_bounds__(256)
void layernorm_k(float* __restrict__ x, const float* __restrict__ g,
                 const float* __restrict__ bt)
{
    __shared__ float sh[8];
    __shared__ float stat[2];
    float* row = x + (long long)blockIdx.x * 1024;
    const int tid  = threadIdx.x;
    const int lane = tid & 31;
    const int wid  = tid >> 5;

    float4 v = ((const float4*)row)[tid];

    float s = v.x + v.y + v.z + v.w;
#pragma unroll
    for (int o = 16; o > 0; o >>= 1) s += __shfl_xor_sync(0xffffffffu, s, o);
    if (lane == 0) sh[wid] = s;
    __syncthreads();
    if (wid == 0) {
        float t = (lane < 8) ? sh[lane] : 0.f;
#pragma unroll
        for (int o = 4; o > 0; o >>= 1) t += __shfl_xor_sync(0xffffffffu, t, o);
        if (lane == 0) stat[0] = t;
    }
    __syncthreads();
    const float mean = stat[0] * (1.f / 1024.f);

    const float dx = v.x - mean, dy = v.y - mean, dz = v.z - mean, dw = v.w - mean;
    float ss = dx * dx + dy * dy + dz * dz + dw * dw;
#pragma unroll
    for (int o = 16; o > 0; o >>= 1) ss += __shfl_xor_sync(0xffffffffu, ss, o);
    __syncthreads();
    if (lane == 0) sh[wid] = ss;
    __syncthreads();
    if (wid == 0) {
        float t = (lane < 8) ? sh[lane] : 0.f;
#pragma unroll
        for (int o = 4; o > 0; o >>= 1) t += __shfl_xor_sync(0xffffffffu, t, o);
        if (lane == 0) stat[1] = t;
    }
    __syncthreads();
    const float inv = rsqrtf(stat[1] * (1.f / 1024.f) + 1e-5f);

    const float4 gg = ((const float4*)g)[tid];
    const float4 bb = ((const float4*)bt)[tid];
    float4 o4;
    o4.x = tf32r(dx * inv * gg.x + bb.x);
    o4.y = tf32r(dy * inv * gg.y + bb.y);
    o4.z = tf32r(dz * inv * gg.z + bb.z);
    o4.w = tf32r(dw * inv * gg.w + bb.w);
    ((float4*)row)[tid] = o4;
}

// ---------------- tiled transpose: out[c, r] = in[r, c] (optional tf32 round) ----------------
__global__ __launch_bounds__(256)
void transpose_k(const float* __restrict__ in, int ldi, long long sIn,
                 float* __restrict__ out, int ldo, long long sOut, int rnd)
{
    __shared__ float t[32][33];
    in  += (long long)blockIdx.z * sIn;
    out += (long long)blockIdx.z * sOut;
    const int r0 = blockIdx.y * 32;
    const int c0 = blockIdx.x * 32;
    const int x = threadIdx.x;   // 32
    const int y = threadIdx.y;   // 8
#pragma unroll
    for (int i = 0; i < 32; i += 8)
        t[y + i][x] = in[(long long)(r0 + y + i) * ldi + c0 + x];
    __syncthreads();
    if (rnd) {
#pragma unroll
        for (int i = 0; i < 32; i += 8)
            out[(long long)(c0 + y + i) * ldo + r0 + x] = tf32r(t[x][y + i]);
    } else {
#pragma unroll
        for (int i = 0; i < 32; i += 8)
            out[(long long)(c0 + y + i) * ldo + r0 + x] = t[x][y + i];
    }
}

// ---------------- launcher ----------------
extern "C" void kernel_launch(void* const* d_in, const int* in_sizes, int n_in,
                              void* d_out, int out_size)
{
    const float* x_spa  = (const float*)d_in[0];
    const float* x_freq = (const float*)d_in[1];
    const float* w_cdc  = (const float*)d_in[2];
    const float* b_cdc  = (const float*)d_in[3];
    const float* w_sv   = (const float*)d_in[4];
    const float* b_sv   = (const float*)d_in[5];
    const float* w_fv   = (const float*)d_in[6];
    const float* b_fv   = (const float*)d_in[7];
    const float* ln_w   = (const float*)d_in[8];
    const float* ln_b   = (const float*)d_in[9];
    const float* w_qk   = (const float*)d_in[10];
    const float* w_spa  = (const float*)d_in[11];
    const float* b_spa  = (const float*)d_in[12];
    const float* w_frq  = (const float*)d_in[13];
    const float* b_frq  = (const float*)d_in[14];

    float* out_spa  = (float*)d_out;
    float* out_freq = (float*)d_out + (long long)NB * NC * HW;

    float *p_x, *p_vspa, *p_vfreq, *p_qk, *p_qT, *p_kw, *p_E, *p_part, *p_inv, *p_bcat;
    float *p_wqkT, *p_wspaT, *p_wfrqT;
    float *p_xspar, *p_xfreqr, *p_wcdcr, *p_wsvr, *p_wfvr;
    cudaGetSymbolAddress((void**)&p_x,      g_x);
    cudaGetSymbolAddress((void**)&p_vspa,   g_vspa);
    cudaGetSymbolAddress((void**)&p_vfreq,  g_vfreq);
    cudaGetSymbolAddress((void**)&p_qk,     g_qk);
    cudaGetSymbolAddress((void**)&p_qT,     g_qT);
    cudaGetSymbolAddress((void**)&p_kw,     g_kw);
    cudaGetSymbolAddress((void**)&p_E,      g_E);
    cudaGetSymbolAddress((void**)&p_part,   g_part);
    cudaGetSymbolAddress((void**)&p_inv,    g_inv);
    cudaGetSymbolAddress((void**)&p_bcat,   g_bcat);
    cudaGetSymbolAddress((void**)&p_wqkT,   g_wqkT);
    cudaGetSymbolAddress((void**)&p_wspaT,  g_wspaT);
    cudaGetSymbolAddress((void**)&p_wfrqT,  g_wfrqT);
    cudaGetSymbolAddress((void**)&p_xspar,  g_xspar);
    cudaGetSymbolAddress((void**)&p_xfreqr, g_xfreqr);
    cudaGetSymbolAddress((void**)&p_wcdcr,  g_wcdcr);
    cudaGetSymbolAddress((void**)&p_wsvr,   g_wsvr);
    cudaGetSymbolAddress((void**)&p_wfvr,   g_wfvr);

    static int smem_set = 0;
    if (!smem_set) {
        cudaFuncSetAttribute(sgemm_tc, cudaFuncAttributeMaxDynamicSharedMemorySize, SMEM_BYTES);
        smem_set = 1;
    }

    const long long sX   = (long long)NC * HW;        // 262144
    const long long sQK  = (long long)NC * 2 * HW;    // 524288
    const long long sQT  = (long long)HW * NC;        // 262144
    const long long sKW  = (long long)NC * 2 * HW;    // 524288 (merged [c,2048])
    const long long sE   = (long long)HW * 2 * HW;    // 2097152
    const dim3 tb(32, 8);
    const float scale = 0.03125f;                     // hw^-0.5 = 1/32

    // rounds (launch idx 0..3)
    round_k<<<(NB * NC * HW / 4 + 255) / 256, 256>>>((const float4*)x_spa,  (float4*)p_xspar,  NB * NC * HW / 4);
    round_k<<<(NB * NC * HW / 4 + 255) / 256, 256>>>((const float4*)x_freq, (float4*)p_xfreqr, NB * NC * HW / 4);
    round_k<<<(NC * 2 * NC / 4 + 255) / 256, 256>>>((const float4*)w_cdc, (float4*)p_wcdcr, NC * 2 * NC / 4);
    round_k<<<(NC * NC / 4 + 255) / 256, 256>>>((const float4*)w_sv, (float4*)p_wsvr, NC * NC / 4);

    // GEMMs at idx 4..6
    sgemm_tc<<<dim3(HW / BN, NC / BM, NB), 128, SMEM_BYTES>>>(       // cdc part 1
        p_wcdcr, 512, 0, p_xspar, 1024, sX, nullptr, 0, b_cdc, nullptr,
        p_x, 1024, sX, 256, 1.f, 0, nullptr, nullptr);
    sgemm_tc<<<dim3(HW / BN, NC / BM, NB), 128, SMEM_BYTES>>>(       // cdc part 2
        p_wcdcr + 256, 512, 0, p_xfreqr, 1024, sX, p_x, sX, nullptr, nullptr,
        p_x, 1024, sX, 256, 1.f, 0, nullptr, nullptr);
    sgemm_tc<<<dim3(HW / BN, NC / BM, NB), 128, SMEM_BYTES>>>(       // v_spa
        p_wsvr, 256, 0, p_xspar, 1024, sX, nullptr, 0, b_sv, nullptr,
        p_vspa, 1024, sX, 256, 1.f, 1, nullptr, nullptr);

    round_k<<<(NC * NC / 4 + 255) / 256, 256>>>((const float4*)w_fv, (float4*)p_wfvr, NC * NC / 4);
    sgemm_tc<<<dim3(HW / BN, NC / BM, NB), 128, SMEM_BYTES>>>(       // v_freq
        p_wfvr, 256, 0, p_xfreqr, 1024, sX, nullptr, 0, b_fv, nullptr,
        p_vfreq, 1024, sX, 256, 1.f, 1, nullptr, nullptr);

    // weight transposes (rounded) + bias concat
    transpose_k<<<dim3(1024 / 32, 2048 / 32, 1), tb>>>(w_qk, 1024, 0, p_wqkT, 2048, 0, 1);
    transpose_k<<<dim3(1024 / 32, 1024 / 32, 1), tb>>>(w_spa, 1024, 0, p_wspaT, 1024, 0, 1);
    transpose_k<<<dim3(1024 / 32, 1024 / 32, 1), tb>>>(w_frq, 1024, 0, p_wfrqT, 1024, 0, 1);
    bcat_k<<<8, 256>>>(b_spa, b_frq, p_bcat);

    // LayerNorm rows of X (writes tf32-rounded)
    layernorm_k<<<NB * NC, 256>>>(p_x, ln_w, ln_b);

    // qk = X @ w_qk^T   [256, 2048] (rounded)
    sgemm_tc<<<dim3(2048 / BN, NC / BM, NB), 128, SMEM_BYTES>>>(
        p_x, 1024, sX, p_wqkT, 2048, 0, nullptr, 0, nullptr, nullptr,
        p_qk, 2048, sQK, 1024, 1.f, 1, nullptr, nullptr);

    // qT[b][n][c] = q[b][c][n]
    transpose_k<<<dim3(HW / 32, NC / 32, NB), tb>>>(p_qk, 2048, sQK, p_qT, 256, sQT, 0);

    // kw = k @ [w_spa^T | w_frq^T]  -> [256, 2048] per batch (rounded)
    sgemm_tc<<<dim3(HW / BN, NC / BM, NB), 128, SMEM_BYTES>>>(
        p_qk + 1024, 2048, sQK, p_wspaT, 1024, 0, nullptr, 0, nullptr, nullptr,
        p_kw, 2048, sKW, 1024, 1.f, 1, nullptr, nullptr);
    sgemm_tc<<<dim3(HW / BN, NC / BM, NB), 128, SMEM_BYTES>>>(
        p_qk + 1024, 2048, sQK, p_wfrqT, 1024, 0, nullptr, 0, nullptr, nullptr,
        p_kw + 1024, 2048, sKW, 1024, 1.f, 1, nullptr, nullptr);

    // merged logits GEMM with fused exp + deterministic row partial sums
    // E[n, 0:2048] = exp(scale * qT @ kw + bcat)   [1024, 2048], K = 256
    sgemm_tc<<<dim3(2048 / BN, HW / BM, NB), 128, SMEM_BYTES>>>(
        p_qT, 256, sQT, p_kw, 2048, sKW, nullptr, 0, nullptr, p_bcat,
        p_E, 2048, sE, 256, scale, 0, nullptr, p_part);

    // inverse row sums (deterministic)
    inv_k<<<(NB * 2 * HW + 255) / 256, 256>>>(p_part, p_inv, NB * 2 * HW);

    // final GEMMs: out = x + (v * inv_cols) @ E_branch
    sgemm_tc<<<dim3(HW / BN, NC / BM, NB), 128, SMEM_BYTES>>>(
        p_vspa, 1024, sX, p_E, 2048, sE, x_spa, sX, nullptr, nullptr,
        out_spa, 1024, sX, 1024, 1.f, 0, p_inv, nullptr);
    sgemm_tc<<<dim3(HW / BN, NC / BM, NB), 128, SMEM_BYTES>>>(
        p_vfreq, 1024, sX, p_E + 1024, 2048, sE, x_freq, sX, nullptr, nullptr,
        out_freq, 1024, sX, 1024, 1.f, 0, p_inv + 1024, nullptr);

    (void)in_sizes; (void)n_in; (void)out_size;
}